// round 9
// baseline (speedup 1.0000x reference)
#include <cuda_runtime.h>
#include <cuda_bf16.h>
#include <math.h>

#define B_  8
#define LQ_ 1024
#define LK_ 1024
#define D_  1024
#define H_  16
#define HD_ 64
#define NTOK (B_ * LQ_)
#define NELEM ((size_t)B_ * LQ_ * D_)

// Scratch (static device globals)
__device__ float g_Q[NELEM];
__device__ float g_K[NELEM];
__device__ float g_V[NELEM];
__device__ float g_G[NELEM];
__device__ float g_O[NELEM];
// head-major [B,H,L,HD] bf16 hi/lo for attention
__device__ __nv_bfloat16 g_Qh[NELEM];
__device__ __nv_bfloat16 g_Ql[NELEM];
__device__ __nv_bfloat16 g_Kh[NELEM];
__device__ __nv_bfloat16 g_Kl[NELEM];
__device__ __nv_bfloat16 g_Vh[NELEM];
__device__ __nv_bfloat16 g_Vl[NELEM];

// ---------------------------------------------------------------------------
// PTX helpers
// ---------------------------------------------------------------------------
__device__ __forceinline__ void ldsm_x4(unsigned* r, unsigned addr) {
    asm volatile("ldmatrix.sync.aligned.m8n8.x4.shared.b16 {%0,%1,%2,%3}, [%4];\n"
                 : "=r"(r[0]), "=r"(r[1]), "=r"(r[2]), "=r"(r[3]) : "r"(addr));
}
__device__ __forceinline__ void ldsm_x4_t(unsigned* r, unsigned addr) {
    asm volatile("ldmatrix.sync.aligned.m8n8.x4.trans.shared.b16 {%0,%1,%2,%3}, [%4];\n"
                 : "=r"(r[0]), "=r"(r[1]), "=r"(r[2]), "=r"(r[3]) : "r"(addr));
}
__device__ __forceinline__ void mma_bf16(float* c, const unsigned* a, const unsigned* b) {
    asm volatile(
        "mma.sync.aligned.m16n8k16.row.col.f32.bf16.bf16.f32 "
        "{%0,%1,%2,%3}, {%4,%5,%6,%7}, {%8,%9}, {%0,%1,%2,%3};\n"
        : "+f"(c[0]), "+f"(c[1]), "+f"(c[2]), "+f"(c[3])
        : "r"(a[0]), "r"(a[1]), "r"(a[2]), "r"(a[3]), "r"(b[0]), "r"(b[1]));
}
__device__ __forceinline__ unsigned smaddr(const void* p) {
    return (unsigned)__cvta_generic_to_shared(p);
}

// ---------------------------------------------------------------------------
// Fused-convert double-buffered bf16x3 GEMM, 512 threads.
// C[n][m] = (A .* A2)[n][:] . W[m][:] + bias[m]
// BM=BN=128, BK=32; 16 warps in 4(m) x 4(n) grid, warp tile 32x32.
// fp32 -> bf16 hi/lo conversion fused into the load path.
// ---------------------------------------------------------------------------
#define PBM 128
#define PBN 128
#define PBK 32
#define PLDA 40
#define PSTAGE (PBM * PLDA)                 // bf16 elements per buffer
#define GEMM_SMEM (2 * 4 * PSTAGE * 2)      // 81920 B

__global__ __launch_bounds__(512) void gemm_f32_bf16x3_kernel(
    const float* __restrict__ A, const float* __restrict__ A2,
    const float* __restrict__ W, const float* __restrict__ bias,
    float* __restrict__ C, int act)
{
    extern __shared__ __nv_bfloat16 sm[];

    const int tid = threadIdx.x;
    const int wid = tid >> 5, lane = tid & 31;
    const int bm = blockIdx.y * PBM, bn = blockIdx.x * PBN;
    const int wm = (wid >> 2) * 32, wn = (wid & 3) * 32;

    const int lr = tid >> 3;          // base row 0..63 (i adds 64)
    const int lc = (tid & 7) * 4;     // fp32 column within 32-wide k-block

    float acc[2][4][4];
#pragma unroll
    for (int a = 0; a < 2; a++)
#pragma unroll
        for (int b = 0; b < 4; b++)
#pragma unroll
            for (int c = 0; c < 4; c++) acc[a][b][c] = 0.0f;

    float4 pa[2], pw[2];

    // ---- prefetch k-block 0 ----
#pragma unroll
    for (int i = 0; i < 2; i++) {
        int r = lr + i * 64;
        pa[i] = *reinterpret_cast<const float4*>(&A[(size_t)(bm + r) * 1024 + lc]);
        pw[i] = *reinterpret_cast<const float4*>(&W[(size_t)(bn + r) * 1024 + lc]);
    }
    if (A2) {
#pragma unroll
        for (int i = 0; i < 2; i++) {
            int r = lr + i * 64;
            float4 g = *reinterpret_cast<const float4*>(&A2[(size_t)(bm + r) * 1024 + lc]);
            pa[i].x *= g.x; pa[i].y *= g.y; pa[i].z *= g.z; pa[i].w *= g.w;
        }
    }

    // ---- store stage 0 ----
    {
        __nv_bfloat16* bAh = sm;
        __nv_bfloat16* bAl = bAh + PSTAGE;
        __nv_bfloat16* bWh = bAl + PSTAGE;
        __nv_bfloat16* bWl = bWh + PSTAGE;
#pragma unroll
        for (int i = 0; i < 2; i++) {
            int r = lr + i * 64;
            float va[4] = {pa[i].x, pa[i].y, pa[i].z, pa[i].w};
            float vw[4] = {pw[i].x, pw[i].y, pw[i].z, pw[i].w};
            __nv_bfloat16 h[4], l[4], hw[4], lw[4];
#pragma unroll
            for (int j = 0; j < 4; j++) {
                h[j] = __float2bfloat16_rn(va[j]);
                l[j] = __float2bfloat16_rn(va[j] - __bfloat162float(h[j]));
                hw[j] = __float2bfloat16_rn(vw[j]);
                lw[j] = __float2bfloat16_rn(vw[j] - __bfloat162float(hw[j]));
            }
            *reinterpret_cast<uint2*>(&bAh[r * PLDA + lc]) = *reinterpret_cast<uint2*>(h);
            *reinterpret_cast<uint2*>(&bAl[r * PLDA + lc]) = *reinterpret_cast<uint2*>(l);
            *reinterpret_cast<uint2*>(&bWh[r * PLDA + lc]) = *reinterpret_cast<uint2*>(hw);
            *reinterpret_cast<uint2*>(&bWl[r * PLDA + lc]) = *reinterpret_cast<uint2*>(lw);
        }
    }
    __syncthreads();

    const int NKB = 1024 / PBK;   // 32
    for (int kb = 0; kb < NKB; kb++) {
        // prefetch next k-block
        if (kb + 1 < NKB) {
            int kcol = (kb + 1) * PBK + lc;
#pragma unroll
            for (int i = 0; i < 2; i++) {
                int r = lr + i * 64;
                pa[i] = *reinterpret_cast<const float4*>(&A[(size_t)(bm + r) * 1024 + kcol]);
                pw[i] = *reinterpret_cast<const float4*>(&W[(size_t)(bn + r) * 1024 + kcol]);
            }
            if (A2) {
#pragma unroll
                for (int i = 0; i < 2; i++) {
                    int r = lr + i * 64;
                    float4 g = *reinterpret_cast<const float4*>(
                        &A2[(size_t)(bm + r) * 1024 + kcol]);
                    pa[i].x *= g.x; pa[i].y *= g.y; pa[i].z *= g.z; pa[i].w *= g.w;
                }
            }
        }

        // compute from stage kb&1
        {
            const __nv_bfloat16* bAh = sm + (size_t)(kb & 1) * 4 * PSTAGE;
            const __nv_bfloat16* bAl = bAh + PSTAGE;
            const __nv_bfloat16* bWh = bAl + PSTAGE;
            const __nv_bfloat16* bWl = bWh + PSTAGE;
#pragma unroll
            for (int kk = 0; kk < PBK; kk += 16) {
                unsigned ah[2][4], al[2][4], bh[2][4], bl[2][4];
#pragma unroll
                for (int mt = 0; mt < 2; mt++) {
                    int row = wm + mt * 16 + (lane & 15);
                    int col = kk + (lane >> 4) * 8;
                    ldsm_x4(ah[mt], smaddr(&bAh[row * PLDA + col]));
                    ldsm_x4(al[mt], smaddr(&bAl[row * PLDA + col]));
                }
#pragma unroll
                for (int p = 0; p < 2; p++) {
                    int row = wn + p * 16 + ((lane >> 4) & 1) * 8 + (lane & 7);
                    int col = kk + ((lane >> 3) & 1) * 8;
                    ldsm_x4(bh[p], smaddr(&bWh[row * PLDA + col]));
                    ldsm_x4(bl[p], smaddr(&bWl[row * PLDA + col]));
                }
#pragma unroll
                for (int mt = 0; mt < 2; mt++) {
#pragma unroll
                    for (int nt = 0; nt < 4; nt++) {
                        unsigned bhf[2] = { bh[nt >> 1][(nt & 1) * 2],
                                            bh[nt >> 1][(nt & 1) * 2 + 1] };
                        unsigned blf[2] = { bl[nt >> 1][(nt & 1) * 2],
                                            bl[nt >> 1][(nt & 1) * 2 + 1] };
                        mma_bf16(acc[mt][nt], ah[mt], bhf);
                        mma_bf16(acc[mt][nt], ah[mt], blf);
                        mma_bf16(acc[mt][nt], al[mt], bhf);
                    }
                }
            }
        }

        // store next stage
        if (kb + 1 < NKB) {
            __nv_bfloat16* bAh = sm + (size_t)((kb + 1) & 1) * 4 * PSTAGE;
            __nv_bfloat16* bAl = bAh + PSTAGE;
            __nv_bfloat16* bWh = bAl + PSTAGE;
            __nv_bfloat16* bWl = bWh + PSTAGE;
#pragma unroll
            for (int i = 0; i < 2; i++) {
                int r = lr + i * 64;
                float va[4] = {pa[i].x, pa[i].y, pa[i].z, pa[i].w};
                float vw[4] = {pw[i].x, pw[i].y, pw[i].z, pw[i].w};
                __nv_bfloat16 h[4], l[4], hw[4], lw[4];
#pragma unroll
                for (int j = 0; j < 4; j++) {
                    h[j] = __float2bfloat16_rn(va[j]);
                    l[j] = __float2bfloat16_rn(va[j] - __bfloat162float(h[j]));
                    hw[j] = __float2bfloat16_rn(vw[j]);
                    lw[j] = __float2bfloat16_rn(vw[j] - __bfloat162float(hw[j]));
                }
                *reinterpret_cast<uint2*>(&bAh[r * PLDA + lc]) = *reinterpret_cast<uint2*>(h);
                *reinterpret_cast<uint2*>(&bAl[r * PLDA + lc]) = *reinterpret_cast<uint2*>(l);
                *reinterpret_cast<uint2*>(&bWh[r * PLDA + lc]) = *reinterpret_cast<uint2*>(hw);
                *reinterpret_cast<uint2*>(&bWl[r * PLDA + lc]) = *reinterpret_cast<uint2*>(lw);
            }
        }
        __syncthreads();
    }

    // epilogue
    const int g = lane >> 2, t = lane & 3;
#pragma unroll
    for (int mt = 0; mt < 2; mt++) {
#pragma unroll
        for (int nt = 0; nt < 4; nt++) {
            int row = bm + wm + mt * 16 + g;
            int col = bn + wn + nt * 8 + t * 2;
            float b0 = bias[col], b1 = bias[col + 1];
            float c0 = acc[mt][nt][0] + b0;
            float c1 = acc[mt][nt][1] + b1;
            float c2 = acc[mt][nt][2] + b0;
            float c3 = acc[mt][nt][3] + b1;
            if (act) {
                c0 = 1.0f / (1.0f + __expf(-c0));
                c1 = 1.0f / (1.0f + __expf(-c1));
                c2 = 1.0f / (1.0f + __expf(-c2));
                c3 = 1.0f / (1.0f + __expf(-c3));
            }
            *reinterpret_cast<float2*>(&C[(size_t)row * 1024 + col]) = make_float2(c0, c1);
            *reinterpret_cast<float2*>(&C[(size_t)(row + 8) * 1024 + col]) = make_float2(c2, c3);
        }
    }
}

// ---------------------------------------------------------------------------
// Fused RoPE + split + transpose to head-major [B,H,L,HD] bf16 hi/lo.
// ---------------------------------------------------------------------------
__global__ void qk_prep_kernel(const float* __restrict__ X,
                               const float* __restrict__ cosb,
                               const float* __restrict__ sinb,
                               __nv_bfloat16* __restrict__ hi,
                               __nv_bfloat16* __restrict__ lo)
{
    int bl = blockIdx.x;
    int b = bl >> 10, l = bl & 1023;
    int h = threadIdx.x >> 4, j = threadIdx.x & 15;
    int d0 = j * 2;

    size_t ibase = (size_t)bl * D_ + h * HD_;
    size_t obase = ((size_t)(b * H_ + h) * LK_ + l) * HD_;
    size_t cbase = (size_t)bl * HD_;

    float x0 = X[ibase + d0],      x1 = X[ibase + d0 + 1];
    float y0 = X[ibase + d0 + 32], y1 = X[ibase + d0 + 33];
    float cA0 = cosb[cbase + d0],      sA0 = sinb[cbase + d0];
    float cA1 = cosb[cbase + d0 + 1],  sA1 = sinb[cbase + d0 + 1];
    float cB0 = cosb[cbase + d0 + 32], sB0 = sinb[cbase + d0 + 32];
    float cB1 = cosb[cbase + d0 + 33], sB1 = sinb[cbase + d0 + 33];

    float r0 = x0 * cA0 - y0 * sA0;
    float r1 = x1 * cA1 - y1 * sA1;
    float r2 = y0 * cB0 + x0 * sB0;
    float r3 = y1 * cB1 + x1 * sB1;

    __nv_bfloat16 h0 = __float2bfloat16_rn(r0), h1 = __float2bfloat16_rn(r1);
    __nv_bfloat16 h2 = __float2bfloat16_rn(r2), h3 = __float2bfloat16_rn(r3);
    __nv_bfloat162 hp0; hp0.x = h0; hp0.y = h1;
    __nv_bfloat162 hp1; hp1.x = h2; hp1.y = h3;
    __nv_bfloat162 lp0;
    lp0.x = __float2bfloat16_rn(r0 - __bfloat162float(h0));
    lp0.y = __float2bfloat16_rn(r1 - __bfloat162float(h1));
    __nv_bfloat162 lp1;
    lp1.x = __float2bfloat16_rn(r2 - __bfloat162float(h2));
    lp1.y = __float2bfloat16_rn(r3 - __bfloat162float(h3));

    *reinterpret_cast<__nv_bfloat162*>(&hi[obase + d0]) = hp0;
    *reinterpret_cast<__nv_bfloat162*>(&hi[obase + d0 + 32]) = hp1;
    *reinterpret_cast<__nv_bfloat162*>(&lo[obase + d0]) = lp0;
    *reinterpret_cast<__nv_bfloat162*>(&lo[obase + d0 + 32]) = lp1;
}

__global__ void v_prep_kernel(const float* __restrict__ X,
                              __nv_bfloat16* __restrict__ hi,
                              __nv_bfloat16* __restrict__ lo)
{
    int bl = blockIdx.x;
    int b = bl >> 10, l = bl & 1023;
    int h = threadIdx.x >> 4, j = threadIdx.x & 15;
    int d0 = j * 4;

    size_t ibase = (size_t)bl * D_ + h * HD_ + d0;
    size_t obase = ((size_t)(b * H_ + h) * LK_ + l) * HD_ + d0;

    float4 v = *reinterpret_cast<const float4*>(&X[ibase]);
    float vv[4] = {v.x, v.y, v.z, v.w};
    __nv_bfloat16 hh[4], ll[4];
#pragma unroll
    for (int i = 0; i < 4; i++) {
        hh[i] = __float2bfloat16_rn(vv[i]);
        ll[i] = __float2bfloat16_rn(vv[i] - __bfloat162float(hh[i]));
    }
    *reinterpret_cast<uint2*>(&hi[obase]) = *reinterpret_cast<uint2*>(hh);
    *reinterpret_cast<uint2*>(&lo[obase]) = *reinterpret_cast<uint2*>(ll);
}

// ---------------------------------------------------------------------------
// Tensor-core flash attention (bf16x3), unchanged (passing since R5).
// ---------------------------------------------------------------------------
#define AP 72
#define ATTN_SMEM (6 * 64 * AP * 2 + 64 * 4)

__global__ __launch_bounds__(128) void attn_mma_kernel(
    const __nv_bfloat16* __restrict__ Qh, const __nv_bfloat16* __restrict__ Ql,
    const __nv_bfloat16* __restrict__ Kh, const __nv_bfloat16* __restrict__ Kl,
    const __nv_bfloat16* __restrict__ Vh, const __nv_bfloat16* __restrict__ Vl,
    const unsigned char* __restrict__ mask, float* __restrict__ O)
{
    extern __shared__ char smraw[];
    __nv_bfloat16* sQh = reinterpret_cast<__nv_bfloat16*>(smraw);
    __nv_bfloat16* sQl = sQh + 64 * AP;
    __nv_bfloat16* sKh = sQl + 64 * AP;
    __nv_bfloat16* sKl = sKh + 64 * AP;
    __nv_bfloat16* sVh = sKl + 64 * AP;
    __nv_bfloat16* sVl = sVh + 64 * AP;
    float* sMask = reinterpret_cast<float*>(sVl + 64 * AP);

    const int tid = threadIdx.x;
    const int w = tid >> 5, lane = tid & 31;
    const int q0 = blockIdx.x * 64;
    const int h = blockIdx.y, b = blockIdx.z;
    const size_t headbase = (size_t)(b * H_ + h) * LK_ * HD_;
    const size_t qbase = headbase + (size_t)q0 * HD_;

#pragma unroll
    for (int it = 0; it < 4; it++) {
        int idx = tid + it * 128;
        int r = idx >> 3, c = (idx & 7) * 8;
        *reinterpret_cast<uint4*>(&sQh[r * AP + c]) =
            *reinterpret_cast<const uint4*>(&Qh[qbase + (size_t)r * HD_ + c]);
        *reinterpret_cast<uint4*>(&sQl[r * AP + c]) =
            *reinterpret_cast<const uint4*>(&Ql[qbase + (size_t)r * HD_ + c]);
    }
    __syncthreads();

    unsigned qh[4][4], ql[4][4];
    {
        int row = w * 16 + (lane & 15);
#pragma unroll
        for (int kk = 0; kk < 4; kk++) {
            int col = kk * 16 + (lane >> 4) * 8;
            ldsm_x4(qh[kk], smaddr(&sQh[row * AP + col]));
            ldsm_x4(ql[kk], smaddr(&sQl[row * AP + col]));
        }
    }

    float m0 = -3.0e38f, m1 = -3.0e38f, l0 = 0.0f, l1 = 0.0f;
    float Oacc[8][4];
#pragma unroll
    for (int nt = 0; nt < 8; nt++)
#pragma unroll
        for (int r = 0; r < 4; r++) Oacc[nt][r] = 0.0f;

    const int t = lane & 3;

    for (int k0 = 0; k0 < LK_; k0 += 64) {
        __syncthreads();
#pragma unroll
        for (int it = 0; it < 4; it++) {
            int idx = tid + it * 128;
            int r = idx >> 3, c = (idx & 7) * 8;
            size_t g = headbase + (size_t)(k0 + r) * HD_ + c;
            *reinterpret_cast<uint4*>(&sKh[r * AP + c]) =
                *reinterpret_cast<const uint4*>(&Kh[g]);
            *reinterpret_cast<uint4*>(&sKl[r * AP + c]) =
                *reinterpret_cast<const uint4*>(&Kl[g]);
            *reinterpret_cast<uint4*>(&sVh[r * AP + c]) =
                *reinterpret_cast<const uint4*>(&Vh[g]);
            *reinterpret_cast<uint4*>(&sVl[r * AP + c]) =
                *reinterpret_cast<const uint4*>(&Vl[g]);
        }
        if (tid < 64)
            sMask[tid] = mask[b * LK_ + k0 + tid] ? -1.0e30f : 0.0f;
        __syncthreads();

        float S[8][4];
#pragma unroll
        for (int nt = 0; nt < 8; nt++)
#pragma unroll
            for (int r = 0; r < 4; r++) S[nt][r] = 0.0f;

#pragma unroll
        for (int p = 0; p < 4; p++) {
#pragma unroll
            for (int kk = 0; kk < 4; kk++) {
                unsigned kbh[4], kbl[4];
                int row = p * 16 + ((lane >> 4) & 1) * 8 + (lane & 7);
                int col = kk * 16 + ((lane >> 3) & 1) * 8;
                ldsm_x4(kbh, smaddr(&sKh[row * AP + col]));
                ldsm_x4(kbl, smaddr(&sKl[row * AP + col]));
#pragma unroll
                for (int sub = 0; sub < 2; sub++) {
                    unsigned bh2[2] = {kbh[sub * 2], kbh[sub * 2 + 1]};
                    unsigned bl2[2] = {kbl[sub * 2], kbl[sub * 2 + 1]};
                    mma_bf16(S[2 * p + sub], qh[kk], bh2);
                    mma_bf16(S[2 * p + sub], qh[kk], bl2);
                    mma_bf16(S[2 * p + sub], ql[kk], bh2);
                }
            }
        }

        float rmax0 = -3.0e38f, rmax1 = -3.0e38f;
#pragma unroll
        for (int nt = 0; nt < 8; nt++) {
            float mv0 = sMask[nt * 8 + t * 2];
            float mv1 = sMask[nt * 8 + t * 2 + 1];
            S[nt][0] = S[nt][0] * 0.125f + mv0;
            S[nt][1] = S[nt][1] * 0.125f + mv1;
            S[nt][2] = S[nt][2] * 0.125f + mv0;
            S[nt][3] = S[nt][3] * 0.125f + mv1;
            rmax0 = fmaxf(rmax0, fmaxf(S[nt][0], S[nt][1]));
            rmax1 = fmaxf(rmax1, fmaxf(S[nt][2], S[nt][3]));
        }
        rmax0 = fmaxf(rmax0, __shfl_xor_sync(0xffffffffu, rmax0, 1));
        rmax0 = fmaxf(rmax0, __shfl_xor_sync(0xffffffffu, rmax0, 2));
        rmax1 = fmaxf(rmax1, __shfl_xor_sync(0xffffffffu, rmax1, 1));
        rmax1 = fmaxf(rmax1, __shfl_xor_sync(0xffffffffu, rmax1, 2));

        float mn0 = fmaxf(m0, rmax0), mn1 = fmaxf(m1, rmax1);
        float a0 = __expf(m0 - mn0), a1 = __expf(m1 - mn1);
        m0 = mn0; m1 = mn1;

        float rs0 = 0.0f, rs1 = 0.0f;
#pragma unroll
        for (int nt = 0; nt < 8; nt++) {
            S[nt][0] = __expf(S[nt][0] - m0);
            S[nt][1] = __expf(S[nt][1] - m0);
            S[nt][2] = __expf(S[nt][2] - m1);
            S[nt][3] = __expf(S[nt][3] - m1);
            rs0 += S[nt][0] + S[nt][1];
            rs1 += S[nt][2] + S[nt][3];
        }
        rs0 += __shfl_xor_sync(0xffffffffu, rs0, 1);
        rs0 += __shfl_xor_sync(0xffffffffu, rs0, 2);
        rs1 += __shfl_xor_sync(0xffffffffu, rs1, 1);
        rs1 += __shfl_xor_sync(0xffffffffu, rs1, 2);
        l0 = l0 * a0 + rs0;
        l1 = l1 * a1 + rs1;
#pragma unroll
        for (int nt = 0; nt < 8; nt++) {
            Oacc[nt][0] *= a0; Oacc[nt][1] *= a0;
            Oacc[nt][2] *= a1; Oacc[nt][3] *= a1;
        }

#pragma unroll
        for (int j = 0; j < 4; j++) {
            unsigned ah4[4], al4[4];
#pragma unroll
            for (int s2 = 0; s2 < 2; s2++) {
                int nt = 2 * j + s2;
                float p0 = S[nt][0], p1 = S[nt][1];
                float p2 = S[nt][2], p3 = S[nt][3];
                __nv_bfloat162 h01 = __floats2bfloat162_rn(p0, p1);
                __nv_bfloat162 h23 = __floats2bfloat162_rn(p2, p3);
                __nv_bfloat162 l01 = __floats2bfloat162_rn(
                    p0 - __bfloat162float(h01.x), p1 - __bfloat162float(h01.y));
                __nv_bfloat162 l23 = __floats2bfloat162_rn(
                    p2 - __bfloat162float(h23.x), p3 - __bfloat162float(h23.y));
                ah4[s2 * 2]     = *reinterpret_cast<unsigned*>(&h01);
                ah4[s2 * 2 + 1] = *reinterpret_cast<unsigned*>(&h23);
                al4[s2 * 2]     = *reinterpret_cast<unsigned*>(&l01);
                al4[s2 * 2 + 1] = *reinterpret_cast<unsigned*>(&l23);
            }
#pragma unroll
            for (int q = 0; q < 4; q++) {
                unsigned vbh[4], vbl[4];
                int row = j * 16 + ((lane >> 3) & 1) * 8 + (lane & 7);
                int col = q * 16 + ((lane >> 4) & 1) * 8;
                ldsm_x4_t(vbh, smaddr(&sVh[row * AP + col]));
                ldsm_x4_t(vbl, smaddr(&sVl[row * AP + col]));
#pragma unroll
                for (int sub = 0; sub < 2; sub++) {
                    unsigned bh2[2] = {vbh[sub * 2], vbh[sub * 2 + 1]};
                    unsigned bl2[2] = {vbl[sub * 2], vbl[sub * 2 + 1]};
                    mma_bf16(Oacc[2 * q + sub], ah4, bh2);
                    mma_bf16(Oacc[2 * q + sub], ah4, bl2);
                    mma_bf16(Oacc[2 * q + sub], al4, bh2);
                }
            }
        }
    }

    float inv0 = 1.0f / l0, inv1 = 1.0f / l1;
    const int g = lane >> 2;
    int row0 = q0 + w * 16 + g;
#pragma unroll
    for (int nt = 0; nt < 8; nt++) {
        int col = h * HD_ + nt * 8 + t * 2;
        *reinterpret_cast<float2*>(
            &O[((size_t)(b * LQ_) + row0) * D_ + col]) =
            make_float2(Oacc[nt][0] * inv0, Oacc[nt][1] * inv0);
        *reinterpret_cast<float2*>(
            &O[((size_t)(b * LQ_) + row0 + 8) * D_ + col]) =
            make_float2(Oacc[nt][2] * inv1, Oacc[nt][3] * inv1);
    }
}

// ---------------------------------------------------------------------------
extern "C" void kernel_launch(void* const* d_in, const int* in_sizes, int n_in,
                              void* d_out, int out_size)
{
    const float* query = (const float*)d_in[0];
    const float* key   = (const float*)d_in[1];
    const float* value = (const float*)d_in[2];
    const float* Wq = (const float*)d_in[3];
    const float* bq = (const float*)d_in[4];
    const float* Wk = (const float*)d_in[5];
    const float* bk = (const float*)d_in[6];
    const float* Wv = (const float*)d_in[7];
    const float* bv = (const float*)d_in[8];
    const float* Wg = (const float*)d_in[9];
    const float* bg = (const float*)d_in[10];
    const float* Wo = (const float*)d_in[11];
    const float* bo = (const float*)d_in[12];
    const float* rc = (const float*)d_in[13];
    const float* rs = (const float*)d_in[14];
    const unsigned char* mask = (const unsigned char*)d_in[15];
    float* out = (float*)d_out;

    float *Qb, *Kb, *Vb, *Gb, *Ob;
    __nv_bfloat16 *Qhh, *Qll, *Khh, *Kll, *Vhh, *Vll;
    cudaGetSymbolAddress((void**)&Qb, g_Q);
    cudaGetSymbolAddress((void**)&Kb, g_K);
    cudaGetSymbolAddress((void**)&Vb, g_V);
    cudaGetSymbolAddress((void**)&Gb, g_G);
    cudaGetSymbolAddress((void**)&Ob, g_O);
    cudaGetSymbolAddress((void**)&Qhh, g_Qh);
    cudaGetSymbolAddress((void**)&Qll, g_Ql);
    cudaGetSymbolAddress((void**)&Khh, g_Kh);
    cudaGetSymbolAddress((void**)&Kll, g_Kl);
    cudaGetSymbolAddress((void**)&Vhh, g_Vh);
    cudaGetSymbolAddress((void**)&Vll, g_Vl);

    cudaFuncSetAttribute(gemm_f32_bf16x3_kernel,
                         cudaFuncAttributeMaxDynamicSharedMemorySize, GEMM_SMEM);
    cudaFuncSetAttribute(attn_mma_kernel,
                         cudaFuncAttributeMaxDynamicSharedMemorySize, ATTN_SMEM);

    dim3 ggrid(D_ / PBN, NTOK / PBM);   // (8, 64)

    // Projections (conversion fused into GEMM loads)
    gemm_f32_bf16x3_kernel<<<ggrid, 512, GEMM_SMEM>>>(query, nullptr, Wq, bq, Qb, 0);
    gemm_f32_bf16x3_kernel<<<ggrid, 512, GEMM_SMEM>>>(query, nullptr, Wg, bg, Gb, 1);
    gemm_f32_bf16x3_kernel<<<ggrid, 512, GEMM_SMEM>>>(key,   nullptr, Wk, bk, Kb, 0);
    gemm_f32_bf16x3_kernel<<<ggrid, 512, GEMM_SMEM>>>(value, nullptr, Wv, bv, Vb, 0);

    // Fused RoPE + split + transpose (Q, K); split + transpose (V)
    qk_prep_kernel<<<B_ * LQ_, 256>>>(Qb, rc, rs, Qhh, Qll);
    qk_prep_kernel<<<B_ * LK_, 256>>>(Kb, rc, rs, Khh, Kll);
    v_prep_kernel<<<B_ * LK_, 256>>>(Vb, Vhh, Vll);

    // Tensor-core attention
    attn_mma_kernel<<<dim3(LQ_ / 64, H_, B_), 128, ATTN_SMEM>>>(
        Qhh, Qll, Khh, Kll, Vhh, Vll, mask, Ob);

    // Output projection with fused gate multiply
    gemm_f32_bf16x3_kernel<<<ggrid, 512, GEMM_SMEM>>>(Ob, Gb, Wo, bo, out, 0);
}

// round 13
// speedup vs baseline: 1.1568x; 1.1568x over previous
#include <cuda_runtime.h>
#include <cuda_bf16.h>
#include <math.h>

#define B_  8
#define LQ_ 1024
#define LK_ 1024
#define D_  1024
#define H_  16
#define HD_ 64
#define NTOK (B_ * LQ_)
#define NELEM ((size_t)B_ * LQ_ * D_)

// Scratch (static device globals)
__device__ float g_Q[NELEM];
__device__ float g_K[NELEM];
__device__ float g_V[NELEM];
__device__ float g_G[NELEM];
__device__ float g_O[NELEM];
__device__ __nv_bfloat16 g_Ah[NELEM];
__device__ __nv_bfloat16 g_Al[NELEM];
__device__ __nv_bfloat16 g_Wh[D_ * D_];
__device__ __nv_bfloat16 g_Wl[D_ * D_];
// head-major [B,H,L,HD] bf16 hi/lo for attention
__device__ __nv_bfloat16 g_Qh[NELEM];
__device__ __nv_bfloat16 g_Ql[NELEM];
__device__ __nv_bfloat16 g_Kh[NELEM];
__device__ __nv_bfloat16 g_Kl[NELEM];
__device__ __nv_bfloat16 g_Vh[NELEM];
__device__ __nv_bfloat16 g_Vl[NELEM];

// ---------------------------------------------------------------------------
// PTX helpers
// ---------------------------------------------------------------------------
__device__ __forceinline__ void ldsm_x4(unsigned* r, unsigned addr) {
    asm volatile("ldmatrix.sync.aligned.m8n8.x4.shared.b16 {%0,%1,%2,%3}, [%4];\n"
                 : "=r"(r[0]), "=r"(r[1]), "=r"(r[2]), "=r"(r[3]) : "r"(addr));
}
__device__ __forceinline__ void ldsm_x4_t(unsigned* r, unsigned addr) {
    asm volatile("ldmatrix.sync.aligned.m8n8.x4.trans.shared.b16 {%0,%1,%2,%3}, [%4];\n"
                 : "=r"(r[0]), "=r"(r[1]), "=r"(r[2]), "=r"(r[3]) : "r"(addr));
}
__device__ __forceinline__ void mma_bf16(float* c, const unsigned* a, const unsigned* b) {
    asm volatile(
        "mma.sync.aligned.m16n8k16.row.col.f32.bf16.bf16.f32 "
        "{%0,%1,%2,%3}, {%4,%5,%6,%7}, {%8,%9}, {%0,%1,%2,%3};\n"
        : "+f"(c[0]), "+f"(c[1]), "+f"(c[2]), "+f"(c[3])
        : "r"(a[0]), "r"(a[1]), "r"(a[2]), "r"(a[3]), "r"(b[0]), "r"(b[1]));
}
__device__ __forceinline__ unsigned smaddr(const void* p) {
    return (unsigned)__cvta_generic_to_shared(p);
}
__device__ __forceinline__ void cp_async16(unsigned dst, const void* src) {
    asm volatile("cp.async.cg.shared.global [%0], [%1], 16;\n"
                 :: "r"(dst), "l"(src));
}
__device__ __forceinline__ void cp_commit() {
    asm volatile("cp.async.commit_group;\n");
}
template <int N>
__device__ __forceinline__ void cp_wait() {
    asm volatile("cp.async.wait_group %0;\n" :: "n"(N));
}

// ---------------------------------------------------------------------------
// Split fp32 -> bf16 hi + lo  (L2-resident, ~5us each)
// ---------------------------------------------------------------------------
__global__ void split_kernel(const float* __restrict__ x,
                             __nv_bfloat16* __restrict__ hi,
                             __nv_bfloat16* __restrict__ lo, int n)
{
    int i = (blockIdx.x * blockDim.x + threadIdx.x) * 4;
    if (i >= n) return;
    float4 v = *reinterpret_cast<const float4*>(x + i);
    float vv[4] = {v.x, v.y, v.z, v.w};
    __nv_bfloat16 h[4], l[4];
#pragma unroll
    for (int j = 0; j < 4; j++) {
        h[j] = __float2bfloat16_rn(vv[j]);
        l[j] = __float2bfloat16_rn(vv[j] - __bfloat162float(h[j]));
    }
    *reinterpret_cast<uint2*>(hi + i) = *reinterpret_cast<uint2*>(h);
    *reinterpret_cast<uint2*>(lo + i) = *reinterpret_cast<uint2*>(l);
}

__global__ void gate_split_kernel(const float* __restrict__ O,
                                  const float* __restrict__ G,
                                  __nv_bfloat16* __restrict__ hi,
                                  __nv_bfloat16* __restrict__ lo, int n)
{
    int i = (blockIdx.x * blockDim.x + threadIdx.x) * 4;
    if (i >= n) return;
    float4 o = *reinterpret_cast<const float4*>(O + i);
    float4 g = *reinterpret_cast<const float4*>(G + i);
    float vv[4] = {o.x * g.x, o.y * g.y, o.z * g.z, o.w * g.w};
    __nv_bfloat16 h[4], l[4];
#pragma unroll
    for (int j = 0; j < 4; j++) {
        h[j] = __float2bfloat16_rn(vv[j]);
        l[j] = __float2bfloat16_rn(vv[j] - __bfloat162float(h[j]));
    }
    *reinterpret_cast<uint2*>(hi + i) = *reinterpret_cast<uint2*>(h);
    *reinterpret_cast<uint2*>(lo + i) = *reinterpret_cast<uint2*>(l);
}

// ---------------------------------------------------------------------------
// cp.async 2-stage pipelined bf16x3 GEMM on pre-split inputs.
// C[n][m] = (Ah+Al)[n][:] . (Wh+Wl)[m][:] + bias[m]
// BM=BN=128, BK=32; 256 threads, 8 warps 2(m) x 4(n), warp tile 64x32.
// ---------------------------------------------------------------------------
#define PBM 128
#define PBN 128
#define PBK 32
#define PLDA 40
#define PSTAGE (PBM * PLDA)                 // bf16 elements per buffer
#define GEMM_SMEM (2 * 4 * PSTAGE * 2)      // 2 stages x 4 buffers x 2B = 81920

__global__ __launch_bounds__(256, 2) void gemm_async_kernel(
    const __nv_bfloat16* __restrict__ Ah, const __nv_bfloat16* __restrict__ Al,
    const __nv_bfloat16* __restrict__ Wh, const __nv_bfloat16* __restrict__ Wl,
    const float* __restrict__ bias, float* __restrict__ C, int act)
{
    extern __shared__ __nv_bfloat16 sm[];

    const int tid = threadIdx.x;
    const int wid = tid >> 5, lane = tid & 31;
    const int bm = blockIdx.y * PBM, bn = blockIdx.x * PBN;
    const int wm = (wid >> 2) * 64, wn = (wid & 3) * 32;

    // copy coords: thread -> (row, 16-elem col half) per 128x32 buffer
    const int cr = tid >> 1;                 // row 0..127
    const int cc = (tid & 1) * 16;           // bf16 col 0 or 16

    float acc[4][4][4];
#pragma unroll
    for (int a = 0; a < 4; a++)
#pragma unroll
        for (int b = 0; b < 4; b++)
#pragma unroll
            for (int c = 0; c < 4; c++) acc[a][b][c] = 0.0f;

    // issue async copy of k-block kb into stage s
    // buffer byte offsets within a stage: Ah=0, Al=PSTAGE*2, Wh=2*PSTAGE*2, Wl=3*PSTAGE*2
    auto copy_stage = [&](int s, int kb) {
        __nv_bfloat16* base = sm + (size_t)s * 4 * PSTAGE;
        const int kc = kb * PBK + cc;
        unsigned d = smaddr(&base[cr * PLDA + cc]);
        const size_t ga = (size_t)(bm + cr) * 1024 + kc;
        const size_t gw = (size_t)(bn + cr) * 1024 + kc;
        cp_async16(d,                          &Ah[ga]);
        cp_async16(d + 16,                     &Ah[ga + 8]);
        cp_async16(d + 1 * PSTAGE * 2,         &Al[ga]);
        cp_async16(d + 1 * PSTAGE * 2 + 16,    &Al[ga + 8]);
        cp_async16(d + 2 * PSTAGE * 2,         &Wh[gw]);
        cp_async16(d + 2 * PSTAGE * 2 + 16,    &Wh[gw + 8]);
        cp_async16(d + 3 * PSTAGE * 2,         &Wl[gw]);
        cp_async16(d + 3 * PSTAGE * 2 + 16,    &Wl[gw + 8]);
    };

    copy_stage(0, 0);
    cp_commit();

    const int NKB = 1024 / PBK;   // 32
    for (int kb = 0; kb < NKB; kb++) {
        if (kb + 1 < NKB) {
            copy_stage((kb + 1) & 1, kb + 1);
            cp_commit();
            cp_wait<1>();          // stage kb's copy complete
        } else {
            cp_wait<0>();
        }
        __syncthreads();

        {
            const __nv_bfloat16* bAh = sm + (size_t)(kb & 1) * 4 * PSTAGE;
            const __nv_bfloat16* bAl = bAh + PSTAGE;
            const __nv_bfloat16* bWh = bAl + PSTAGE;
            const __nv_bfloat16* bWl = bWh + PSTAGE;
#pragma unroll
            for (int kk = 0; kk < PBK; kk += 16) {
                unsigned ah[4][4], al[4][4], bh[2][4], bl[2][4];
#pragma unroll
                for (int mt = 0; mt < 4; mt++) {
                    int row = wm + mt * 16 + (lane & 15);
                    int col = kk + (lane >> 4) * 8;
                    ldsm_x4(ah[mt], smaddr(&bAh[row * PLDA + col]));
                    ldsm_x4(al[mt], smaddr(&bAl[row * PLDA + col]));
                }
#pragma unroll
                for (int p = 0; p < 2; p++) {
                    int row = wn + p * 16 + ((lane >> 4) & 1) * 8 + (lane & 7);
                    int col = kk + ((lane >> 3) & 1) * 8;
                    ldsm_x4(bh[p], smaddr(&bWh[row * PLDA + col]));
                    ldsm_x4(bl[p], smaddr(&bWl[row * PLDA + col]));
                }
#pragma unroll
                for (int mt = 0; mt < 4; mt++) {
#pragma unroll
                    for (int nt = 0; nt < 4; nt++) {
                        unsigned bhf[2] = { bh[nt >> 1][(nt & 1) * 2],
                                            bh[nt >> 1][(nt & 1) * 2 + 1] };
                        unsigned blf[2] = { bl[nt >> 1][(nt & 1) * 2],
                                            bl[nt >> 1][(nt & 1) * 2 + 1] };
                        mma_bf16(acc[mt][nt], ah[mt], bhf);
                        mma_bf16(acc[mt][nt], ah[mt], blf);
                        mma_bf16(acc[mt][nt], al[mt], bhf);
                    }
                }
            }
        }
        __syncthreads();   // all warps done reading stage kb before its reuse
    }

    // epilogue
    const int g = lane >> 2, t = lane & 3;
#pragma unroll
    for (int mt = 0; mt < 4; mt++) {
#pragma unroll
        for (int nt = 0; nt < 4; nt++) {
            int row = bm + wm + mt * 16 + g;
            int col = bn + wn + nt * 8 + t * 2;
            float b0 = bias[col], b1 = bias[col + 1];
            float c0 = acc[mt][nt][0] + b0;
            float c1 = acc[mt][nt][1] + b1;
            float c2 = acc[mt][nt][2] + b0;
            float c3 = acc[mt][nt][3] + b1;
            if (act) {
                c0 = 1.0f / (1.0f + __expf(-c0));
                c1 = 1.0f / (1.0f + __expf(-c1));
                c2 = 1.0f / (1.0f + __expf(-c2));
                c3 = 1.0f / (1.0f + __expf(-c3));
            }
            *reinterpret_cast<float2*>(&C[(size_t)row * 1024 + col]) = make_float2(c0, c1);
            *reinterpret_cast<float2*>(&C[(size_t)(row + 8) * 1024 + col]) = make_float2(c2, c3);
        }
    }
}

// ---------------------------------------------------------------------------
// Fused RoPE + split + transpose to head-major [B,H,L,HD] bf16 hi/lo.
// ---------------------------------------------------------------------------
__global__ void qk_prep_kernel(const float* __restrict__ X,
                               const float* __restrict__ cosb,
                               const float* __restrict__ sinb,
                               __nv_bfloat16* __restrict__ hi,
                               __nv_bfloat16* __restrict__ lo)
{
    int bl = blockIdx.x;
    int b = bl >> 10, l = bl & 1023;
    int h = threadIdx.x >> 4, j = threadIdx.x & 15;
    int d0 = j * 2;

    size_t ibase = (size_t)bl * D_ + h * HD_;
    size_t obase = ((size_t)(b * H_ + h) * LK_ + l) * HD_;
    size_t cbase = (size_t)bl * HD_;

    float x0 = X[ibase + d0],      x1 = X[ibase + d0 + 1];
    float y0 = X[ibase + d0 + 32], y1 = X[ibase + d0 + 33];
    float cA0 = cosb[cbase + d0],      sA0 = sinb[cbase + d0];
    float cA1 = cosb[cbase + d0 + 1],  sA1 = sinb[cbase + d0 + 1];
    float cB0 = cosb[cbase + d0 + 32], sB0 = sinb[cbase + d0 + 32];
    float cB1 = cosb[cbase + d0 + 33], sB1 = sinb[cbase + d0 + 33];

    float r0 = x0 * cA0 - y0 * sA0;
    float r1 = x1 * cA1 - y1 * sA1;
    float r2 = y0 * cB0 + x0 * sB0;
    float r3 = y1 * cB1 + x1 * sB1;

    __nv_bfloat16 h0 = __float2bfloat16_rn(r0), h1 = __float2bfloat16_rn(r1);
    __nv_bfloat16 h2 = __float2bfloat16_rn(r2), h3 = __float2bfloat16_rn(r3);
    __nv_bfloat162 hp0; hp0.x = h0; hp0.y = h1;
    __nv_bfloat162 hp1; hp1.x = h2; hp1.y = h3;
    __nv_bfloat162 lp0;
    lp0.x = __float2bfloat16_rn(r0 - __bfloat162float(h0));
    lp0.y = __float2bfloat16_rn(r1 - __bfloat162float(h1));
    __nv_bfloat162 lp1;
    lp1.x = __float2bfloat16_rn(r2 - __bfloat162float(h2));
    lp1.y = __float2bfloat16_rn(r3 - __bfloat162float(h3));

    *reinterpret_cast<__nv_bfloat162*>(&hi[obase + d0]) = hp0;
    *reinterpret_cast<__nv_bfloat162*>(&hi[obase + d0 + 32]) = hp1;
    *reinterpret_cast<__nv_bfloat162*>(&lo[obase + d0]) = lp0;
    *reinterpret_cast<__nv_bfloat162*>(&lo[obase + d0 + 32]) = lp1;
}

__global__ void v_prep_kernel(const float* __restrict__ X,
                              __nv_bfloat16* __restrict__ hi,
                              __nv_bfloat16* __restrict__ lo)
{
    int bl = blockIdx.x;
    int b = bl >> 10, l = bl & 1023;
    int h = threadIdx.x >> 4, j = threadIdx.x & 15;
    int d0 = j * 4;

    size_t ibase = (size_t)bl * D_ + h * HD_ + d0;
    size_t obase = ((size_t)(b * H_ + h) * LK_ + l) * HD_ + d0;

    float4 v = *reinterpret_cast<const float4*>(&X[ibase]);
    float vv[4] = {v.x, v.y, v.z, v.w};
    __nv_bfloat16 hh[4], ll[4];
#pragma unroll
    for (int i = 0; i < 4; i++) {
        hh[i] = __float2bfloat16_rn(vv[i]);
        ll[i] = __float2bfloat16_rn(vv[i] - __bfloat162float(hh[i]));
    }
    *reinterpret_cast<uint2*>(&hi[obase]) = *reinterpret_cast<uint2*>(hh);
    *reinterpret_cast<uint2*>(&lo[obase]) = *reinterpret_cast<uint2*>(ll);
}

// ---------------------------------------------------------------------------
// Tensor-core flash attention (bf16x3), unchanged (passing since R5).
// ---------------------------------------------------------------------------
#define AP 72
#define ATTN_SMEM (6 * 64 * AP * 2 + 64 * 4)

__global__ __launch_bounds__(128) void attn_mma_kernel(
    const __nv_bfloat16* __restrict__ Qh, const __nv_bfloat16* __restrict__ Ql,
    const __nv_bfloat16* __restrict__ Kh, const __nv_bfloat16* __restrict__ Kl,
    const __nv_bfloat16* __restrict__ Vh, const __nv_bfloat16* __restrict__ Vl,
    const unsigned char* __restrict__ mask, float* __restrict__ O)
{
    extern __shared__ char smraw[];
    __nv_bfloat16* sQh = reinterpret_cast<__nv_bfloat16*>(smraw);
    __nv_bfloat16* sQl = sQh + 64 * AP;
    __nv_bfloat16* sKh = sQl + 64 * AP;
    __nv_bfloat16* sKl = sKh + 64 * AP;
    __nv_bfloat16* sVh = sKl + 64 * AP;
    __nv_bfloat16* sVl = sVh + 64 * AP;
    float* sMask = reinterpret_cast<float*>(sVl + 64 * AP);

    const int tid = threadIdx.x;
    const int w = tid >> 5, lane = tid & 31;
    const int q0 = blockIdx.x * 64;
    const int h = blockIdx.y, b = blockIdx.z;
    const size_t headbase = (size_t)(b * H_ + h) * LK_ * HD_;
    const size_t qbase = headbase + (size_t)q0 * HD_;

#pragma unroll
    for (int it = 0; it < 4; it++) {
        int idx = tid + it * 128;
        int r = idx >> 3, c = (idx & 7) * 8;
        *reinterpret_cast<uint4*>(&sQh[r * AP + c]) =
            *reinterpret_cast<const uint4*>(&Qh[qbase + (size_t)r * HD_ + c]);
        *reinterpret_cast<uint4*>(&sQl[r * AP + c]) =
            *reinterpret_cast<const uint4*>(&Ql[qbase + (size_t)r * HD_ + c]);
    }
    __syncthreads();

    unsigned qh[4][4], ql[4][4];
    {
        int row = w * 16 + (lane & 15);
#pragma unroll
        for (int kk = 0; kk < 4; kk++) {
            int col = kk * 16 + (lane >> 4) * 8;
            ldsm_x4(qh[kk], smaddr(&sQh[row * AP + col]));
            ldsm_x4(ql[kk], smaddr(&sQl[row * AP + col]));
        }
    }

    float m0 = -3.0e38f, m1 = -3.0e38f, l0 = 0.0f, l1 = 0.0f;
    float Oacc[8][4];
#pragma unroll
    for (int nt = 0; nt < 8; nt++)
#pragma unroll
        for (int r = 0; r < 4; r++) Oacc[nt][r] = 0.0f;

    const int t = lane & 3;

    for (int k0 = 0; k0 < LK_; k0 += 64) {
        __syncthreads();
#pragma unroll
        for (int it = 0; it < 4; it++) {
            int idx = tid + it * 128;
            int r = idx >> 3, c = (idx & 7) * 8;
            size_t g = headbase + (size_t)(k0 + r) * HD_ + c;
            *reinterpret_cast<uint4*>(&sKh[r * AP + c]) =
                *reinterpret_cast<const uint4*>(&Kh[g]);
            *reinterpret_cast<uint4*>(&sKl[r * AP + c]) =
                *reinterpret_cast<const uint4*>(&Kl[g]);
            *reinterpret_cast<uint4*>(&sVh[r * AP + c]) =
                *reinterpret_cast<const uint4*>(&Vh[g]);
            *reinterpret_cast<uint4*>(&sVl[r * AP + c]) =
                *reinterpret_cast<const uint4*>(&Vl[g]);
        }
        if (tid < 64)
            sMask[tid] = mask[b * LK_ + k0 + tid] ? -1.0e30f : 0.0f;
        __syncthreads();

        float S[8][4];
#pragma unroll
        for (int nt = 0; nt < 8; nt++)
#pragma unroll
            for (int r = 0; r < 4; r++) S[nt][r] = 0.0f;

#pragma unroll
        for (int p = 0; p < 4; p++) {
#pragma unroll
            for (int kk = 0; kk < 4; kk++) {
                unsigned kbh[4], kbl[4];
                int row = p * 16 + ((lane >> 4) & 1) * 8 + (lane & 7);
                int col = kk * 16 + ((lane >> 3) & 1) * 8;
                ldsm_x4(kbh, smaddr(&sKh[row * AP + col]));
                ldsm_x4(kbl, smaddr(&sKl[row * AP + col]));
#pragma unroll
                for (int sub = 0; sub < 2; sub++) {
                    unsigned bh2[2] = {kbh[sub * 2], kbh[sub * 2 + 1]};
                    unsigned bl2[2] = {kbl[sub * 2], kbl[sub * 2 + 1]};
                    mma_bf16(S[2 * p + sub], qh[kk], bh2);
                    mma_bf16(S[2 * p + sub], qh[kk], bl2);
                    mma_bf16(S[2 * p + sub], ql[kk], bh2);
                }
            }
        }

        float rmax0 = -3.0e38f, rmax1 = -3.0e38f;
#pragma unroll
        for (int nt = 0; nt < 8; nt++) {
            float mv0 = sMask[nt * 8 + t * 2];
            float mv1 = sMask[nt * 8 + t * 2 + 1];
            S[nt][0] = S[nt][0] * 0.125f + mv0;
            S[nt][1] = S[nt][1] * 0.125f + mv1;
            S[nt][2] = S[nt][2] * 0.125f + mv0;
            S[nt][3] = S[nt][3] * 0.125f + mv1;
            rmax0 = fmaxf(rmax0, fmaxf(S[nt][0], S[nt][1]));
            rmax1 = fmaxf(rmax1, fmaxf(S[nt][2], S[nt][3]));
        }
        rmax0 = fmaxf(rmax0, __shfl_xor_sync(0xffffffffu, rmax0, 1));
        rmax0 = fmaxf(rmax0, __shfl_xor_sync(0xffffffffu, rmax0, 2));
        rmax1 = fmaxf(rmax1, __shfl_xor_sync(0xffffffffu, rmax1, 1));
        rmax1 = fmaxf(rmax1, __shfl_xor_sync(0xffffffffu, rmax1, 2));

        float mn0 = fmaxf(m0, rmax0), mn1 = fmaxf(m1, rmax1);
        float a0 = __expf(m0 - mn0), a1 = __expf(m1 - mn1);
        m0 = mn0; m1 = mn1;

        float rs0 = 0.0f, rs1 = 0.0f;
#pragma unroll
        for (int nt = 0; nt < 8; nt++) {
            S[nt][0] = __expf(S[nt][0] - m0);
            S[nt][1] = __expf(S[nt][1] - m0);
            S[nt][2] = __expf(S[nt][2] - m1);
            S[nt][3] = __expf(S[nt][3] - m1);
            rs0 += S[nt][0] + S[nt][1];
            rs1 += S[nt][2] + S[nt][3];
        }
        rs0 += __shfl_xor_sync(0xffffffffu, rs0, 1);
        rs0 += __shfl_xor_sync(0xffffffffu, rs0, 2);
        rs1 += __shfl_xor_sync(0xffffffffu, rs1, 1);
        rs1 += __shfl_xor_sync(0xffffffffu, rs1, 2);
        l0 = l0 * a0 + rs0;
        l1 = l1 * a1 + rs1;
#pragma unroll
        for (int nt = 0; nt < 8; nt++) {
            Oacc[nt][0] *= a0; Oacc[nt][1] *= a0;
            Oacc[nt][2] *= a1; Oacc[nt][3] *= a1;
        }

#pragma unroll
        for (int j = 0; j < 4; j++) {
            unsigned ah4[4], al4[4];
#pragma unroll
            for (int s2 = 0; s2 < 2; s2++) {
                int nt = 2 * j + s2;
                float p0 = S[nt][0], p1 = S[nt][1];
                float p2 = S[nt][2], p3 = S[nt][3];
                __nv_bfloat162 h01 = __floats2bfloat162_rn(p0, p1);
                __nv_bfloat162 h23 = __floats2bfloat162_rn(p2, p3);
                __nv_bfloat162 l01 = __floats2bfloat162_rn(
                    p0 - __bfloat162float(h01.x), p1 - __bfloat162float(h01.y));
                __nv_bfloat162 l23 = __floats2bfloat162_rn(
                    p2 - __bfloat162float(h23.x), p3 - __bfloat162float(h23.y));
                ah4[s2 * 2]     = *reinterpret_cast<unsigned*>(&h01);
                ah4[s2 * 2 + 1] = *reinterpret_cast<unsigned*>(&h23);
                al4[s2 * 2]     = *reinterpret_cast<unsigned*>(&l01);
                al4[s2 * 2 + 1] = *reinterpret_cast<unsigned*>(&l23);
            }
#pragma unroll
            for (int q = 0; q < 4; q++) {
                unsigned vbh[4], vbl[4];
                int row = j * 16 + ((lane >> 3) & 1) * 8 + (lane & 7);
                int col = q * 16 + ((lane >> 4) & 1) * 8;
                ldsm_x4_t(vbh, smaddr(&sVh[row * AP + col]));
                ldsm_x4_t(vbl, smaddr(&sVl[row * AP + col]));
#pragma unroll
                for (int sub = 0; sub < 2; sub++) {
                    unsigned bh2[2] = {vbh[sub * 2], vbh[sub * 2 + 1]};
                    unsigned bl2[2] = {vbl[sub * 2], vbl[sub * 2 + 1]};
                    mma_bf16(Oacc[2 * q + sub], ah4, bh2);
                    mma_bf16(Oacc[2 * q + sub], ah4, bl2);
                    mma_bf16(Oacc[2 * q + sub], al4, bh2);
                }
            }
        }
    }

    float inv0 = 1.0f / l0, inv1 = 1.0f / l1;
    const int g = lane >> 2;
    int row0 = q0 + w * 16 + g;
#pragma unroll
    for (int nt = 0; nt < 8; nt++) {
        int col = h * HD_ + nt * 8 + t * 2;
        *reinterpret_cast<float2*>(
            &O[((size_t)(b * LQ_) + row0) * D_ + col]) =
            make_float2(Oacc[nt][0] * inv0, Oacc[nt][1] * inv0);
        *reinterpret_cast<float2*>(
            &O[((size_t)(b * LQ_) + row0 + 8) * D_ + col]) =
            make_float2(Oacc[nt][2] * inv1, Oacc[nt][3] * inv1);
    }
}

// ---------------------------------------------------------------------------
extern "C" void kernel_launch(void* const* d_in, const int* in_sizes, int n_in,
                              void* d_out, int out_size)
{
    const float* query = (const float*)d_in[0];
    const float* key   = (const float*)d_in[1];
    const float* value = (const float*)d_in[2];
    const float* Wq = (const float*)d_in[3];
    const float* bq = (const float*)d_in[4];
    const float* Wk = (const float*)d_in[5];
    const float* bk = (const float*)d_in[6];
    const float* Wv = (const float*)d_in[7];
    const float* bv = (const float*)d_in[8];
    const float* Wg = (const float*)d_in[9];
    const float* bg = (const float*)d_in[10];
    const float* Wo = (const float*)d_in[11];
    const float* bo = (const float*)d_in[12];
    const float* rc = (const float*)d_in[13];
    const float* rs = (const float*)d_in[14];
    const unsigned char* mask = (const unsigned char*)d_in[15];
    float* out = (float*)d_out;

    float *Qb, *Kb, *Vb, *Gb, *Ob;
    __nv_bfloat16 *Ah, *Al, *Wh, *Wl;
    __nv_bfloat16 *Qhh, *Qll, *Khh, *Kll, *Vhh, *Vll;
    cudaGetSymbolAddress((void**)&Qb, g_Q);
    cudaGetSymbolAddress((void**)&Kb, g_K);
    cudaGetSymbolAddress((void**)&Vb, g_V);
    cudaGetSymbolAddress((void**)&Gb, g_G);
    cudaGetSymbolAddress((void**)&Ob, g_O);
    cudaGetSymbolAddress((void**)&Ah, g_Ah);
    cudaGetSymbolAddress((void**)&Al, g_Al);
    cudaGetSymbolAddress((void**)&Wh, g_Wh);
    cudaGetSymbolAddress((void**)&Wl, g_Wl);
    cudaGetSymbolAddress((void**)&Qhh, g_Qh);
    cudaGetSymbolAddress((void**)&Qll, g_Ql);
    cudaGetSymbolAddress((void**)&Khh, g_Kh);
    cudaGetSymbolAddress((void**)&Kll, g_Kl);
    cudaGetSymbolAddress((void**)&Vhh, g_Vh);
    cudaGetSymbolAddress((void**)&Vll, g_Vl);

    cudaFuncSetAttribute(gemm_async_kernel,
                         cudaFuncAttributeMaxDynamicSharedMemorySize, GEMM_SMEM);
    cudaFuncSetAttribute(attn_mma_kernel,
                         cudaFuncAttributeMaxDynamicSharedMemorySize, ATTN_SMEM);

    const int nw = D_ * D_;
    const int na = (int)NELEM;
    dim3 ggrid(D_ / PBN, NTOK / PBM);   // (8, 64)

    // Q projection + gate (both consume query)
    split_kernel<<<na / 1024, 256>>>(query, Ah, Al, na);
    split_kernel<<<nw / 1024, 256>>>(Wq, Wh, Wl, nw);
    gemm_async_kernel<<<ggrid, 256, GEMM_SMEM>>>(Ah, Al, Wh, Wl, bq, Qb, 0);
    split_kernel<<<nw / 1024, 256>>>(Wg, Wh, Wl, nw);
    gemm_async_kernel<<<ggrid, 256, GEMM_SMEM>>>(Ah, Al, Wh, Wl, bg, Gb, 1);

    // K projection
    split_kernel<<<na / 1024, 256>>>(key, Ah, Al, na);
    split_kernel<<<nw / 1024, 256>>>(Wk, Wh, Wl, nw);
    gemm_async_kernel<<<ggrid, 256, GEMM_SMEM>>>(Ah, Al, Wh, Wl, bk, Kb, 0);

    // V projection
    split_kernel<<<na / 1024, 256>>>(value, Ah, Al, na);
    split_kernel<<<nw / 1024, 256>>>(Wv, Wh, Wl, nw);
    gemm_async_kernel<<<ggrid, 256, GEMM_SMEM>>>(Ah, Al, Wh, Wl, bv, Vb, 0);

    // Fused RoPE + split + transpose (Q, K); split + transpose (V)
    qk_prep_kernel<<<B_ * LQ_, 256>>>(Qb, rc, rs, Qhh, Qll);
    qk_prep_kernel<<<B_ * LK_, 256>>>(Kb, rc, rs, Khh, Kll);
    v_prep_kernel<<<B_ * LK_, 256>>>(Vb, Vhh, Vll);

    // Tensor-core attention
    attn_mma_kernel<<<dim3(LQ_ / 64, H_, B_), 128, ATTN_SMEM>>>(
        Qhh, Qll, Khh, Kll, Vhh, Vll, mask, Ob);

    // Gate-multiply + split, then output projection
    gate_split_kernel<<<na / 1024, 256>>>(Ob, Gb, Ah, Al, na);
    split_kernel<<<nw / 1024, 256>>>(Wo, Wh, Wl, nw);
    gemm_async_kernel<<<ggrid, 256, GEMM_SMEM>>>(Ah, Al, Wh, Wl, bo, out, 0);
}

// round 14
// speedup vs baseline: 1.1709x; 1.0121x over previous
#include <cuda_runtime.h>
#include <cuda_bf16.h>
#include <math.h>

#define B_  8
#define LQ_ 1024
#define LK_ 1024
#define D_  1024
#define H_  16
#define HD_ 64
#define NTOK (B_ * LQ_)
#define NELEM ((size_t)B_ * LQ_ * D_)
#define NW (D_ * D_)

// Scratch (static device globals)
__device__ float g_Q[NELEM];
__device__ float g_K[NELEM];
__device__ float g_V[NELEM];
__device__ float g_G[NELEM];
__device__ float g_O[NELEM];
// activation splits: slot 0=query(->gateO reuse), 1=key, 2=value
__device__ __nv_bfloat16 g_Xh[3 * NELEM];
__device__ __nv_bfloat16 g_Xl[3 * NELEM];
// weight splits: slots 0..4 = Wq, Wg, Wk, Wv, Wo
__device__ __nv_bfloat16 g_Wh5[5 * NW];
__device__ __nv_bfloat16 g_Wl5[5 * NW];
// head-major [B,H,L,HD] bf16 hi/lo for attention
__device__ __nv_bfloat16 g_Qh[NELEM];
__device__ __nv_bfloat16 g_Ql[NELEM];
__device__ __nv_bfloat16 g_Kh[NELEM];
__device__ __nv_bfloat16 g_Kl[NELEM];
__device__ __nv_bfloat16 g_Vh[NELEM];
__device__ __nv_bfloat16 g_Vl[NELEM];

// ---------------------------------------------------------------------------
// PTX helpers
// ---------------------------------------------------------------------------
__device__ __forceinline__ void ldsm_x4(unsigned* r, unsigned addr) {
    asm volatile("ldmatrix.sync.aligned.m8n8.x4.shared.b16 {%0,%1,%2,%3}, [%4];\n"
                 : "=r"(r[0]), "=r"(r[1]), "=r"(r[2]), "=r"(r[3]) : "r"(addr));
}
__device__ __forceinline__ void ldsm_x4_t(unsigned* r, unsigned addr) {
    asm volatile("ldmatrix.sync.aligned.m8n8.x4.trans.shared.b16 {%0,%1,%2,%3}, [%4];\n"
                 : "=r"(r[0]), "=r"(r[1]), "=r"(r[2]), "=r"(r[3]) : "r"(addr));
}
__device__ __forceinline__ void mma_bf16(float* c, const unsigned* a, const unsigned* b) {
    asm volatile(
        "mma.sync.aligned.m16n8k16.row.col.f32.bf16.bf16.f32 "
        "{%0,%1,%2,%3}, {%4,%5,%6,%7}, {%8,%9}, {%0,%1,%2,%3};\n"
        : "+f"(c[0]), "+f"(c[1]), "+f"(c[2]), "+f"(c[3])
        : "r"(a[0]), "r"(a[1]), "r"(a[2]), "r"(a[3]), "r"(b[0]), "r"(b[1]));
}
__device__ __forceinline__ unsigned smaddr(const void* p) {
    return (unsigned)__cvta_generic_to_shared(p);
}
__device__ __forceinline__ void cp_async16(unsigned dst, const void* src) {
    asm volatile("cp.async.cg.shared.global [%0], [%1], 16;\n"
                 :: "r"(dst), "l"(src));
}
__device__ __forceinline__ void cp_commit() {
    asm volatile("cp.async.commit_group;\n");
}
template <int N>
__device__ __forceinline__ void cp_wait() {
    asm volatile("cp.async.wait_group %0;\n" :: "n"(N));
}

// ---------------------------------------------------------------------------
// Split helpers
// ---------------------------------------------------------------------------
__device__ __forceinline__ void split4(const float* src, __nv_bfloat16* hi,
                                       __nv_bfloat16* lo, size_t i)
{
    float4 v = *reinterpret_cast<const float4*>(src + i);
    float vv[4] = {v.x, v.y, v.z, v.w};
    __nv_bfloat16 h[4], l[4];
#pragma unroll
    for (int j = 0; j < 4; j++) {
        h[j] = __float2bfloat16_rn(vv[j]);
        l[j] = __float2bfloat16_rn(vv[j] - __bfloat162float(h[j]));
    }
    *reinterpret_cast<uint2*>(hi + i) = *reinterpret_cast<uint2*>(h);
    *reinterpret_cast<uint2*>(lo + i) = *reinterpret_cast<uint2*>(l);
}

// All 5 weights in one launch. 1024 blocks per matrix.
__global__ void split_w_all_kernel(const float* __restrict__ W0,
                                   const float* __restrict__ W1,
                                   const float* __restrict__ W2,
                                   const float* __restrict__ W3,
                                   const float* __restrict__ W4,
                                   __nv_bfloat16* __restrict__ hi,
                                   __nv_bfloat16* __restrict__ lo)
{
    int m = blockIdx.x >> 10;                 // matrix slot
    int blk = blockIdx.x & 1023;
    size_t i = ((size_t)blk * 256 + threadIdx.x) * 4;
    const float* W = (m == 0) ? W0 : (m == 1) ? W1 : (m == 2) ? W2
                   : (m == 3) ? W3 : W4;
    split4(W, hi + (size_t)m * NW, lo + (size_t)m * NW, i);
}

// query/key/value in one launch. 8192 blocks per tensor.
__global__ void split_act3_kernel(const float* __restrict__ X0,
                                  const float* __restrict__ X1,
                                  const float* __restrict__ X2,
                                  __nv_bfloat16* __restrict__ hi,
                                  __nv_bfloat16* __restrict__ lo)
{
    int m = blockIdx.x >> 13;                 // tensor slot
    int blk = blockIdx.x & 8191;
    size_t i = ((size_t)blk * 256 + threadIdx.x) * 4;
    const float* X = (m == 0) ? X0 : (m == 1) ? X1 : X2;
    split4(X, hi + (size_t)m * NELEM, lo + (size_t)m * NELEM, i);
}

__global__ void gate_split_kernel(const float* __restrict__ O,
                                  const float* __restrict__ G,
                                  __nv_bfloat16* __restrict__ hi,
                                  __nv_bfloat16* __restrict__ lo, int n)
{
    int i = (blockIdx.x * blockDim.x + threadIdx.x) * 4;
    if (i >= n) return;
    float4 o = *reinterpret_cast<const float4*>(O + i);
    float4 g = *reinterpret_cast<const float4*>(G + i);
    float vv[4] = {o.x * g.x, o.y * g.y, o.z * g.z, o.w * g.w};
    __nv_bfloat16 h[4], l[4];
#pragma unroll
    for (int j = 0; j < 4; j++) {
        h[j] = __float2bfloat16_rn(vv[j]);
        l[j] = __float2bfloat16_rn(vv[j] - __bfloat162float(h[j]));
    }
    *reinterpret_cast<uint2*>(hi + i) = *reinterpret_cast<uint2*>(h);
    *reinterpret_cast<uint2*>(lo + i) = *reinterpret_cast<uint2*>(l);
}

// ---------------------------------------------------------------------------
// cp.async 2-stage pipelined bf16x3 GEMM on pre-split inputs (R13, passing).
// ---------------------------------------------------------------------------
#define PBM 128
#define PBN 128
#define PBK 32
#define PLDA 40
#define PSTAGE (PBM * PLDA)
#define GEMM_SMEM (2 * 4 * PSTAGE * 2)      // 81920 B

__global__ __launch_bounds__(256, 2) void gemm_async_kernel(
    const __nv_bfloat16* __restrict__ Ah, const __nv_bfloat16* __restrict__ Al,
    const __nv_bfloat16* __restrict__ Wh, const __nv_bfloat16* __restrict__ Wl,
    const float* __restrict__ bias, float* __restrict__ C, int act)
{
    extern __shared__ __nv_bfloat16 sm[];

    const int tid = threadIdx.x;
    const int wid = tid >> 5, lane = tid & 31;
    const int bm = blockIdx.y * PBM, bn = blockIdx.x * PBN;
    const int wm = (wid >> 2) * 64, wn = (wid & 3) * 32;

    const int cr = tid >> 1;
    const int cc = (tid & 1) * 16;

    float acc[4][4][4];
#pragma unroll
    for (int a = 0; a < 4; a++)
#pragma unroll
        for (int b = 0; b < 4; b++)
#pragma unroll
            for (int c = 0; c < 4; c++) acc[a][b][c] = 0.0f;

    auto copy_stage = [&](int s, int kb) {
        __nv_bfloat16* base = sm + (size_t)s * 4 * PSTAGE;
        const int kc = kb * PBK + cc;
        unsigned d = smaddr(&base[cr * PLDA + cc]);
        const size_t ga = (size_t)(bm + cr) * 1024 + kc;
        const size_t gw = (size_t)(bn + cr) * 1024 + kc;
        cp_async16(d,                          &Ah[ga]);
        cp_async16(d + 16,                     &Ah[ga + 8]);
        cp_async16(d + 1 * PSTAGE * 2,         &Al[ga]);
        cp_async16(d + 1 * PSTAGE * 2 + 16,    &Al[ga + 8]);
        cp_async16(d + 2 * PSTAGE * 2,         &Wh[gw]);
        cp_async16(d + 2 * PSTAGE * 2 + 16,    &Wh[gw + 8]);
        cp_async16(d + 3 * PSTAGE * 2,         &Wl[gw]);
        cp_async16(d + 3 * PSTAGE * 2 + 16,    &Wl[gw + 8]);
    };

    copy_stage(0, 0);
    cp_commit();

    const int NKB = 1024 / PBK;
    for (int kb = 0; kb < NKB; kb++) {
        if (kb + 1 < NKB) {
            copy_stage((kb + 1) & 1, kb + 1);
            cp_commit();
            cp_wait<1>();
        } else {
            cp_wait<0>();
        }
        __syncthreads();

        {
            const __nv_bfloat16* bAh = sm + (size_t)(kb & 1) * 4 * PSTAGE;
            const __nv_bfloat16* bAl = bAh + PSTAGE;
            const __nv_bfloat16* bWh = bAl + PSTAGE;
            const __nv_bfloat16* bWl = bWh + PSTAGE;
#pragma unroll
            for (int kk = 0; kk < PBK; kk += 16) {
                unsigned ah[4][4], al[4][4], bh[2][4], bl[2][4];
#pragma unroll
                for (int mt = 0; mt < 4; mt++) {
                    int row = wm + mt * 16 + (lane & 15);
                    int col = kk + (lane >> 4) * 8;
                    ldsm_x4(ah[mt], smaddr(&bAh[row * PLDA + col]));
                    ldsm_x4(al[mt], smaddr(&bAl[row * PLDA + col]));
                }
#pragma unroll
                for (int p = 0; p < 2; p++) {
                    int row = wn + p * 16 + ((lane >> 4) & 1) * 8 + (lane & 7);
                    int col = kk + ((lane >> 3) & 1) * 8;
                    ldsm_x4(bh[p], smaddr(&bWh[row * PLDA + col]));
                    ldsm_x4(bl[p], smaddr(&bWl[row * PLDA + col]));
                }
#pragma unroll
                for (int mt = 0; mt < 4; mt++) {
#pragma unroll
                    for (int nt = 0; nt < 4; nt++) {
                        unsigned bhf[2] = { bh[nt >> 1][(nt & 1) * 2],
                                            bh[nt >> 1][(nt & 1) * 2 + 1] };
                        unsigned blf[2] = { bl[nt >> 1][(nt & 1) * 2],
                                            bl[nt >> 1][(nt & 1) * 2 + 1] };
                        mma_bf16(acc[mt][nt], ah[mt], bhf);
                        mma_bf16(acc[mt][nt], ah[mt], blf);
                        mma_bf16(acc[mt][nt], al[mt], bhf);
                    }
                }
            }
        }
        __syncthreads();
    }

    const int g = lane >> 2, t = lane & 3;
#pragma unroll
    for (int mt = 0; mt < 4; mt++) {
#pragma unroll
        for (int nt = 0; nt < 4; nt++) {
            int row = bm + wm + mt * 16 + g;
            int col = bn + wn + nt * 8 + t * 2;
            float b0 = bias[col], b1 = bias[col + 1];
            float c0 = acc[mt][nt][0] + b0;
            float c1 = acc[mt][nt][1] + b1;
            float c2 = acc[mt][nt][2] + b0;
            float c3 = acc[mt][nt][3] + b1;
            if (act) {
                c0 = 1.0f / (1.0f + __expf(-c0));
                c1 = 1.0f / (1.0f + __expf(-c1));
                c2 = 1.0f / (1.0f + __expf(-c2));
                c3 = 1.0f / (1.0f + __expf(-c3));
            }
            *reinterpret_cast<float2*>(&C[(size_t)row * 1024 + col]) = make_float2(c0, c1);
            *reinterpret_cast<float2*>(&C[(size_t)(row + 8) * 1024 + col]) = make_float2(c2, c3);
        }
    }
}

// ---------------------------------------------------------------------------
// Fused RoPE + split + transpose; Q and K in one launch (blockIdx.y selects).
// ---------------------------------------------------------------------------
__global__ void qk_prep2_kernel(const float* __restrict__ Qsrc,
                                const float* __restrict__ Ksrc,
                                const float* __restrict__ cosb,
                                const float* __restrict__ sinb,
                                __nv_bfloat16* __restrict__ Qhi,
                                __nv_bfloat16* __restrict__ Qlo,
                                __nv_bfloat16* __restrict__ Khi,
                                __nv_bfloat16* __restrict__ Klo)
{
    const float* X = blockIdx.y ? Ksrc : Qsrc;
    __nv_bfloat16* hi = blockIdx.y ? Khi : Qhi;
    __nv_bfloat16* lo = blockIdx.y ? Klo : Qlo;

    int bl = blockIdx.x;
    int b = bl >> 10, l = bl & 1023;
    int h = threadIdx.x >> 4, j = threadIdx.x & 15;
    int d0 = j * 2;

    size_t ibase = (size_t)bl * D_ + h * HD_;
    size_t obase = ((size_t)(b * H_ + h) * LK_ + l) * HD_;
    size_t cbase = (size_t)bl * HD_;

    float x0 = X[ibase + d0],      x1 = X[ibase + d0 + 1];
    float y0 = X[ibase + d0 + 32], y1 = X[ibase + d0 + 33];
    float cA0 = cosb[cbase + d0],      sA0 = sinb[cbase + d0];
    float cA1 = cosb[cbase + d0 + 1],  sA1 = sinb[cbase + d0 + 1];
    float cB0 = cosb[cbase + d0 + 32], sB0 = sinb[cbase + d0 + 32];
    float cB1 = cosb[cbase + d0 + 33], sB1 = sinb[cbase + d0 + 33];

    float r0 = x0 * cA0 - y0 * sA0;
    float r1 = x1 * cA1 - y1 * sA1;
    float r2 = y0 * cB0 + x0 * sB0;
    float r3 = y1 * cB1 + x1 * sB1;

    __nv_bfloat16 h0 = __float2bfloat16_rn(r0), h1 = __float2bfloat16_rn(r1);
    __nv_bfloat16 h2 = __float2bfloat16_rn(r2), h3 = __float2bfloat16_rn(r3);
    __nv_bfloat162 hp0; hp0.x = h0; hp0.y = h1;
    __nv_bfloat162 hp1; hp1.x = h2; hp1.y = h3;
    __nv_bfloat162 lp0;
    lp0.x = __float2bfloat16_rn(r0 - __bfloat162float(h0));
    lp0.y = __float2bfloat16_rn(r1 - __bfloat162float(h1));
    __nv_bfloat162 lp1;
    lp1.x = __float2bfloat16_rn(r2 - __bfloat162float(h2));
    lp1.y = __float2bfloat16_rn(r3 - __bfloat162float(h3));

    *reinterpret_cast<__nv_bfloat162*>(&hi[obase + d0]) = hp0;
    *reinterpret_cast<__nv_bfloat162*>(&hi[obase + d0 + 32]) = hp1;
    *reinterpret_cast<__nv_bfloat162*>(&lo[obase + d0]) = lp0;
    *reinterpret_cast<__nv_bfloat162*>(&lo[obase + d0 + 32]) = lp1;
}

__global__ void v_prep_kernel(const float* __restrict__ X,
                              __nv_bfloat16* __restrict__ hi,
                              __nv_bfloat16* __restrict__ lo)
{
    int bl = blockIdx.x;
    int b = bl >> 10, l = bl & 1023;
    int h = threadIdx.x >> 4, j = threadIdx.x & 15;
    int d0 = j * 4;

    size_t ibase = (size_t)bl * D_ + h * HD_ + d0;
    size_t obase = ((size_t)(b * H_ + h) * LK_ + l) * HD_ + d0;

    float4 v = *reinterpret_cast<const float4*>(&X[ibase]);
    float vv[4] = {v.x, v.y, v.z, v.w};
    __nv_bfloat16 hh[4], ll[4];
#pragma unroll
    for (int i = 0; i < 4; i++) {
        hh[i] = __float2bfloat16_rn(vv[i]);
        ll[i] = __float2bfloat16_rn(vv[i] - __bfloat162float(hh[i]));
    }
    *reinterpret_cast<uint2*>(&hi[obase]) = *reinterpret_cast<uint2*>(hh);
    *reinterpret_cast<uint2*>(&lo[obase]) = *reinterpret_cast<uint2*>(ll);
}

// ---------------------------------------------------------------------------
// Tensor-core flash attention (bf16x3), unchanged (passing since R5).
// ---------------------------------------------------------------------------
#define AP 72
#define ATTN_SMEM (6 * 64 * AP * 2 + 64 * 4)

__global__ __launch_bounds__(128) void attn_mma_kernel(
    const __nv_bfloat16* __restrict__ Qh, const __nv_bfloat16* __restrict__ Ql,
    const __nv_bfloat16* __restrict__ Kh, const __nv_bfloat16* __restrict__ Kl,
    const __nv_bfloat16* __restrict__ Vh, const __nv_bfloat16* __restrict__ Vl,
    const unsigned char* __restrict__ mask, float* __restrict__ O)
{
    extern __shared__ char smraw[];
    __nv_bfloat16* sQh = reinterpret_cast<__nv_bfloat16*>(smraw);
    __nv_bfloat16* sQl = sQh + 64 * AP;
    __nv_bfloat16* sKh = sQl + 64 * AP;
    __nv_bfloat16* sKl = sKh + 64 * AP;
    __nv_bfloat16* sVh = sKl + 64 * AP;
    __nv_bfloat16* sVl = sVh + 64 * AP;
    float* sMask = reinterpret_cast<float*>(sVl + 64 * AP);

    const int tid = threadIdx.x;
    const int w = tid >> 5, lane = tid & 31;
    const int q0 = blockIdx.x * 64;
    const int h = blockIdx.y, b = blockIdx.z;
    const size_t headbase = (size_t)(b * H_ + h) * LK_ * HD_;
    const size_t qbase = headbase + (size_t)q0 * HD_;

#pragma unroll
    for (int it = 0; it < 4; it++) {
        int idx = tid + it * 128;
        int r = idx >> 3, c = (idx & 7) * 8;
        *reinterpret_cast<uint4*>(&sQh[r * AP + c]) =
            *reinterpret_cast<const uint4*>(&Qh[qbase + (size_t)r * HD_ + c]);
        *reinterpret_cast<uint4*>(&sQl[r * AP + c]) =
            *reinterpret_cast<const uint4*>(&Ql[qbase + (size_t)r * HD_ + c]);
    }
    __syncthreads();

    unsigned qh[4][4], ql[4][4];
    {
        int row = w * 16 + (lane & 15);
#pragma unroll
        for (int kk = 0; kk < 4; kk++) {
            int col = kk * 16 + (lane >> 4) * 8;
            ldsm_x4(qh[kk], smaddr(&sQh[row * AP + col]));
            ldsm_x4(ql[kk], smaddr(&sQl[row * AP + col]));
        }
    }

    float m0 = -3.0e38f, m1 = -3.0e38f, l0 = 0.0f, l1 = 0.0f;
    float Oacc[8][4];
#pragma unroll
    for (int nt = 0; nt < 8; nt++)
#pragma unroll
        for (int r = 0; r < 4; r++) Oacc[nt][r] = 0.0f;

    const int t = lane & 3;

    for (int k0 = 0; k0 < LK_; k0 += 64) {
        __syncthreads();
#pragma unroll
        for (int it = 0; it < 4; it++) {
            int idx = tid + it * 128;
            int r = idx >> 3, c = (idx & 7) * 8;
            size_t g = headbase + (size_t)(k0 + r) * HD_ + c;
            *reinterpret_cast<uint4*>(&sKh[r * AP + c]) =
                *reinterpret_cast<const uint4*>(&Kh[g]);
            *reinterpret_cast<uint4*>(&sKl[r * AP + c]) =
                *reinterpret_cast<const uint4*>(&Kl[g]);
            *reinterpret_cast<uint4*>(&sVh[r * AP + c]) =
                *reinterpret_cast<const uint4*>(&Vh[g]);
            *reinterpret_cast<uint4*>(&sVl[r * AP + c]) =
                *reinterpret_cast<const uint4*>(&Vl[g]);
        }
        if (tid < 64)
            sMask[tid] = mask[b * LK_ + k0 + tid] ? -1.0e30f : 0.0f;
        __syncthreads();

        float S[8][4];
#pragma unroll
        for (int nt = 0; nt < 8; nt++)
#pragma unroll
            for (int r = 0; r < 4; r++) S[nt][r] = 0.0f;

#pragma unroll
        for (int p = 0; p < 4; p++) {
#pragma unroll
            for (int kk = 0; kk < 4; kk++) {
                unsigned kbh[4], kbl[4];
                int row = p * 16 + ((lane >> 4) & 1) * 8 + (lane & 7);
                int col = kk * 16 + ((lane >> 3) & 1) * 8;
                ldsm_x4(kbh, smaddr(&sKh[row * AP + col]));
                ldsm_x4(kbl, smaddr(&sKl[row * AP + col]));
#pragma unroll
                for (int sub = 0; sub < 2; sub++) {
                    unsigned bh2[2] = {kbh[sub * 2], kbh[sub * 2 + 1]};
                    unsigned bl2[2] = {kbl[sub * 2], kbl[sub * 2 + 1]};
                    mma_bf16(S[2 * p + sub], qh[kk], bh2);
                    mma_bf16(S[2 * p + sub], qh[kk], bl2);
                    mma_bf16(S[2 * p + sub], ql[kk], bh2);
                }
            }
        }

        float rmax0 = -3.0e38f, rmax1 = -3.0e38f;
#pragma unroll
        for (int nt = 0; nt < 8; nt++) {
            float mv0 = sMask[nt * 8 + t * 2];
            float mv1 = sMask[nt * 8 + t * 2 + 1];
            S[nt][0] = S[nt][0] * 0.125f + mv0;
            S[nt][1] = S[nt][1] * 0.125f + mv1;
            S[nt][2] = S[nt][2] * 0.125f + mv0;
            S[nt][3] = S[nt][3] * 0.125f + mv1;
            rmax0 = fmaxf(rmax0, fmaxf(S[nt][0], S[nt][1]));
            rmax1 = fmaxf(rmax1, fmaxf(S[nt][2], S[nt][3]));
        }
        rmax0 = fmaxf(rmax0, __shfl_xor_sync(0xffffffffu, rmax0, 1));
        rmax0 = fmaxf(rmax0, __shfl_xor_sync(0xffffffffu, rmax0, 2));
        rmax1 = fmaxf(rmax1, __shfl_xor_sync(0xffffffffu, rmax1, 1));
        rmax1 = fmaxf(rmax1, __shfl_xor_sync(0xffffffffu, rmax1, 2));

        float mn0 = fmaxf(m0, rmax0), mn1 = fmaxf(m1, rmax1);
        float a0 = __expf(m0 - mn0), a1 = __expf(m1 - mn1);
        m0 = mn0; m1 = mn1;

        float rs0 = 0.0f, rs1 = 0.0f;
#pragma unroll
        for (int nt = 0; nt < 8; nt++) {
            S[nt][0] = __expf(S[nt][0] - m0);
            S[nt][1] = __expf(S[nt][1] - m0);
            S[nt][2] = __expf(S[nt][2] - m1);
            S[nt][3] = __expf(S[nt][3] - m1);
            rs0 += S[nt][0] + S[nt][1];
            rs1 += S[nt][2] + S[nt][3];
        }
        rs0 += __shfl_xor_sync(0xffffffffu, rs0, 1);
        rs0 += __shfl_xor_sync(0xffffffffu, rs0, 2);
        rs1 += __shfl_xor_sync(0xffffffffu, rs1, 1);
        rs1 += __shfl_xor_sync(0xffffffffu, rs1, 2);
        l0 = l0 * a0 + rs0;
        l1 = l1 * a1 + rs1;
#pragma unroll
        for (int nt = 0; nt < 8; nt++) {
            Oacc[nt][0] *= a0; Oacc[nt][1] *= a0;
            Oacc[nt][2] *= a1; Oacc[nt][3] *= a1;
        }

#pragma unroll
        for (int j = 0; j < 4; j++) {
            unsigned ah4[4], al4[4];
#pragma unroll
            for (int s2 = 0; s2 < 2; s2++) {
                int nt = 2 * j + s2;
                float p0 = S[nt][0], p1 = S[nt][1];
                float p2 = S[nt][2], p3 = S[nt][3];
                __nv_bfloat162 h01 = __floats2bfloat162_rn(p0, p1);
                __nv_bfloat162 h23 = __floats2bfloat162_rn(p2, p3);
                __nv_bfloat162 l01 = __floats2bfloat162_rn(
                    p0 - __bfloat162float(h01.x), p1 - __bfloat162float(h01.y));
                __nv_bfloat162 l23 = __floats2bfloat162_rn(
                    p2 - __bfloat162float(h23.x), p3 - __bfloat162float(h23.y));
                ah4[s2 * 2]     = *reinterpret_cast<unsigned*>(&h01);
                ah4[s2 * 2 + 1] = *reinterpret_cast<unsigned*>(&h23);
                al4[s2 * 2]     = *reinterpret_cast<unsigned*>(&l01);
                al4[s2 * 2 + 1] = *reinterpret_cast<unsigned*>(&l23);
            }
#pragma unroll
            for (int q = 0; q < 4; q++) {
                unsigned vbh[4], vbl[4];
                int row = j * 16 + ((lane >> 3) & 1) * 8 + (lane & 7);
                int col = q * 16 + ((lane >> 4) & 1) * 8;
                ldsm_x4_t(vbh, smaddr(&sVh[row * AP + col]));
                ldsm_x4_t(vbl, smaddr(&sVl[row * AP + col]));
#pragma unroll
                for (int sub = 0; sub < 2; sub++) {
                    unsigned bh2[2] = {vbh[sub * 2], vbh[sub * 2 + 1]};
                    unsigned bl2[2] = {vbl[sub * 2], vbl[sub * 2 + 1]};
                    mma_bf16(Oacc[2 * q + sub], ah4, bh2);
                    mma_bf16(Oacc[2 * q + sub], ah4, bl2);
                    mma_bf16(Oacc[2 * q + sub], al4, bh2);
                }
            }
        }
    }

    float inv0 = 1.0f / l0, inv1 = 1.0f / l1;
    const int g = lane >> 2;
    int row0 = q0 + w * 16 + g;
#pragma unroll
    for (int nt = 0; nt < 8; nt++) {
        int col = h * HD_ + nt * 8 + t * 2;
        *reinterpret_cast<float2*>(
            &O[((size_t)(b * LQ_) + row0) * D_ + col]) =
            make_float2(Oacc[nt][0] * inv0, Oacc[nt][1] * inv0);
        *reinterpret_cast<float2*>(
            &O[((size_t)(b * LQ_) + row0 + 8) * D_ + col]) =
            make_float2(Oacc[nt][2] * inv1, Oacc[nt][3] * inv1);
    }
}

// ---------------------------------------------------------------------------
extern "C" void kernel_launch(void* const* d_in, const int* in_sizes, int n_in,
                              void* d_out, int out_size)
{
    const float* query = (const float*)d_in[0];
    const float* key   = (const float*)d_in[1];
    const float* value = (const float*)d_in[2];
    const float* Wq = (const float*)d_in[3];
    const float* bq = (const float*)d_in[4];
    const float* Wk = (const float*)d_in[5];
    const float* bk = (const float*)d_in[6];
    const float* Wv = (const float*)d_in[7];
    const float* bv = (const float*)d_in[8];
    const float* Wg = (const float*)d_in[9];
    const float* bg = (const float*)d_in[10];
    const float* Wo = (const float*)d_in[11];
    const float* bo = (const float*)d_in[12];
    const float* rc = (const float*)d_in[13];
    const float* rs = (const float*)d_in[14];
    const unsigned char* mask = (const unsigned char*)d_in[15];
    float* out = (float*)d_out;

    float *Qb, *Kb, *Vb, *Gb, *Ob;
    __nv_bfloat16 *Xh, *Xl, *Wh5, *Wl5;
    __nv_bfloat16 *Qhh, *Qll, *Khh, *Kll, *Vhh, *Vll;
    cudaGetSymbolAddress((void**)&Qb, g_Q);
    cudaGetSymbolAddress((void**)&Kb, g_K);
    cudaGetSymbolAddress((void**)&Vb, g_V);
    cudaGetSymbolAddress((void**)&Gb, g_G);
    cudaGetSymbolAddress((void**)&Ob, g_O);
    cudaGetSymbolAddress((void**)&Xh, g_Xh);
    cudaGetSymbolAddress((void**)&Xl, g_Xl);
    cudaGetSymbolAddress((void**)&Wh5, g_Wh5);
    cudaGetSymbolAddress((void**)&Wl5, g_Wl5);
    cudaGetSymbolAddress((void**)&Qhh, g_Qh);
    cudaGetSymbolAddress((void**)&Qll, g_Ql);
    cudaGetSymbolAddress((void**)&Khh, g_Kh);
    cudaGetSymbolAddress((void**)&Kll, g_Kl);
    cudaGetSymbolAddress((void**)&Vhh, g_Vh);
    cudaGetSymbolAddress((void**)&Vll, g_Vl);

    cudaFuncSetAttribute(gemm_async_kernel,
                         cudaFuncAttributeMaxDynamicSharedMemorySize, GEMM_SMEM);
    cudaFuncSetAttribute(attn_mma_kernel,
                         cudaFuncAttributeMaxDynamicSharedMemorySize, ATTN_SMEM);

    const int na = (int)NELEM;
    dim3 ggrid(D_ / PBN, NTOK / PBM);   // (8, 64)

    // All splits up front (2 launches)
    split_w_all_kernel<<<5 * 1024, 256>>>(Wq, Wg, Wk, Wv, Wo, Wh5, Wl5);
    split_act3_kernel<<<3 * 8192, 256>>>(query, key, value, Xh, Xl);

    // 4 projections back-to-back (slots: act 0=q,1=k,2=v; w 0=Wq,1=Wg,2=Wk,3=Wv,4=Wo)
    gemm_async_kernel<<<ggrid, 256, GEMM_SMEM>>>(
        Xh, Xl, Wh5, Wl5, bq, Qb, 0);
    gemm_async_kernel<<<ggrid, 256, GEMM_SMEM>>>(
        Xh, Xl, Wh5 + (size_t)1 * NW, Wl5 + (size_t)1 * NW, bg, Gb, 1);
    gemm_async_kernel<<<ggrid, 256, GEMM_SMEM>>>(
        Xh + NELEM, Xl + NELEM, Wh5 + (size_t)2 * NW, Wl5 + (size_t)2 * NW, bk, Kb, 0);
    gemm_async_kernel<<<ggrid, 256, GEMM_SMEM>>>(
        Xh + 2 * NELEM, Xl + 2 * NELEM, Wh5 + (size_t)3 * NW, Wl5 + (size_t)3 * NW,
        bv, Vb, 0);

    // RoPE+split+transpose for Q,K (one launch) and V
    qk_prep2_kernel<<<dim3(B_ * LK_, 2), 256>>>(Qb, Kb, rc, rs, Qhh, Qll, Khh, Kll);
    v_prep_kernel<<<B_ * LK_, 256>>>(Vb, Vhh, Vll);

    // Tensor-core attention
    attn_mma_kernel<<<dim3(LQ_ / 64, H_, B_), 128, ATTN_SMEM>>>(
        Qhh, Qll, Khh, Kll, Vhh, Vll, mask, Ob);

    // Gate-multiply + split into act slot 0, then output projection
    gate_split_kernel<<<na / 1024, 256>>>(Ob, Gb, Xh, Xl, na);
    gemm_async_kernel<<<ggrid, 256, GEMM_SMEM>>>(
        Xh, Xl, Wh5 + (size_t)4 * NW, Wl5 + (size_t)4 * NW, bo, out, 0);
}

// round 15
// speedup vs baseline: 1.2031x; 1.0275x over previous
#include <cuda_runtime.h>
#include <cuda_bf16.h>
#include <math.h>

#define B_  8
#define LQ_ 1024
#define LK_ 1024
#define D_  1024
#define H_  16
#define HD_ 64
#define NTOK (B_ * LQ_)
#define NELEM ((size_t)B_ * LQ_ * D_)
#define NW (D_ * D_)

// Scratch (static device globals)
__device__ float g_Q[NELEM];
__device__ float g_K[NELEM];
__device__ float g_V[NELEM];
__device__ float g_G[NELEM];
__device__ float g_O[NELEM];
// activation splits: slot 0=query(->gateO reuse), 1=key, 2=value
__device__ __nv_bfloat16 g_Xh[3 * NELEM];
__device__ __nv_bfloat16 g_Xl[3 * NELEM];
// weight splits: slots 0..4 = Wq, Wg, Wk, Wv, Wo
__device__ __nv_bfloat16 g_Wh5[5 * NW];
__device__ __nv_bfloat16 g_Wl5[5 * NW];
// head-major [B,H,L,HD] bf16 hi/lo for attention
__device__ __nv_bfloat16 g_Qh[NELEM];
__device__ __nv_bfloat16 g_Ql[NELEM];
__device__ __nv_bfloat16 g_Kh[NELEM];
__device__ __nv_bfloat16 g_Kl[NELEM];
__device__ __nv_bfloat16 g_Vh[NELEM];
__device__ __nv_bfloat16 g_Vl[NELEM];

// ---------------------------------------------------------------------------
// PTX helpers
// ---------------------------------------------------------------------------
__device__ __forceinline__ void ldsm_x4(unsigned* r, unsigned addr) {
    asm volatile("ldmatrix.sync.aligned.m8n8.x4.shared.b16 {%0,%1,%2,%3}, [%4];\n"
                 : "=r"(r[0]), "=r"(r[1]), "=r"(r[2]), "=r"(r[3]) : "r"(addr));
}
__device__ __forceinline__ void ldsm_x4_t(unsigned* r, unsigned addr) {
    asm volatile("ldmatrix.sync.aligned.m8n8.x4.trans.shared.b16 {%0,%1,%2,%3}, [%4];\n"
                 : "=r"(r[0]), "=r"(r[1]), "=r"(r[2]), "=r"(r[3]) : "r"(addr));
}
__device__ __forceinline__ void mma_bf16(float* c, const unsigned* a, const unsigned* b) {
    asm volatile(
        "mma.sync.aligned.m16n8k16.row.col.f32.bf16.bf16.f32 "
        "{%0,%1,%2,%3}, {%4,%5,%6,%7}, {%8,%9}, {%0,%1,%2,%3};\n"
        : "+f"(c[0]), "+f"(c[1]), "+f"(c[2]), "+f"(c[3])
        : "r"(a[0]), "r"(a[1]), "r"(a[2]), "r"(a[3]), "r"(b[0]), "r"(b[1]));
}
__device__ __forceinline__ unsigned smaddr(const void* p) {
    return (unsigned)__cvta_generic_to_shared(p);
}
__device__ __forceinline__ void cp_async16(unsigned dst, const void* src) {
    asm volatile("cp.async.cg.shared.global [%0], [%1], 16;\n"
                 :: "r"(dst), "l"(src));
}
__device__ __forceinline__ void cp_commit() {
    asm volatile("cp.async.commit_group;\n");
}
template <int N>
__device__ __forceinline__ void cp_wait() {
    asm volatile("cp.async.wait_group %0;\n" :: "n"(N));
}

// ---------------------------------------------------------------------------
// Split helpers
// ---------------------------------------------------------------------------
__device__ __forceinline__ void split4(const float* src, __nv_bfloat16* hi,
                                       __nv_bfloat16* lo, size_t i)
{
    float4 v = *reinterpret_cast<const float4*>(src + i);
    float vv[4] = {v.x, v.y, v.z, v.w};
    __nv_bfloat16 h[4], l[4];
#pragma unroll
    for (int j = 0; j < 4; j++) {
        h[j] = __float2bfloat16_rn(vv[j]);
        l[j] = __float2bfloat16_rn(vv[j] - __bfloat162float(h[j]));
    }
    *reinterpret_cast<uint2*>(hi + i) = *reinterpret_cast<uint2*>(h);
    *reinterpret_cast<uint2*>(lo + i) = *reinterpret_cast<uint2*>(l);
}

__global__ void split_w_all_kernel(const float* __restrict__ W0,
                                   const float* __restrict__ W1,
                                   const float* __restrict__ W2,
                                   const float* __restrict__ W3,
                                   const float* __restrict__ W4,
                                   __nv_bfloat16* __restrict__ hi,
                                   __nv_bfloat16* __restrict__ lo)
{
    int m = blockIdx.x >> 10;
    int blk = blockIdx.x & 1023;
    size_t i = ((size_t)blk * 256 + threadIdx.x) * 4;
    const float* W = (m == 0) ? W0 : (m == 1) ? W1 : (m == 2) ? W2
                   : (m == 3) ? W3 : W4;
    split4(W, hi + (size_t)m * NW, lo + (size_t)m * NW, i);
}

__global__ void split_act3_kernel(const float* __restrict__ X0,
                                  const float* __restrict__ X1,
                                  const float* __restrict__ X2,
                                  __nv_bfloat16* __restrict__ hi,
                                  __nv_bfloat16* __restrict__ lo)
{
    int m = blockIdx.x >> 13;
    int blk = blockIdx.x & 8191;
    size_t i = ((size_t)blk * 256 + threadIdx.x) * 4;
    const float* X = (m == 0) ? X0 : (m == 1) ? X1 : X2;
    split4(X, hi + (size_t)m * NELEM, lo + (size_t)m * NELEM, i);
}

__global__ void gate_split_kernel(const float* __restrict__ O,
                                  const float* __restrict__ G,
                                  __nv_bfloat16* __restrict__ hi,
                                  __nv_bfloat16* __restrict__ lo, int n)
{
    int i = (blockIdx.x * blockDim.x + threadIdx.x) * 4;
    if (i >= n) return;
    float4 o = *reinterpret_cast<const float4*>(O + i);
    float4 g = *reinterpret_cast<const float4*>(G + i);
    float vv[4] = {o.x * g.x, o.y * g.y, o.z * g.z, o.w * g.w};
    __nv_bfloat16 h[4], l[4];
#pragma unroll
    for (int j = 0; j < 4; j++) {
        h[j] = __float2bfloat16_rn(vv[j]);
        l[j] = __float2bfloat16_rn(vv[j] - __bfloat162float(h[j]));
    }
    *reinterpret_cast<uint2*>(hi + i) = *reinterpret_cast<uint2*>(h);
    *reinterpret_cast<uint2*>(lo + i) = *reinterpret_cast<uint2*>(l);
}

// ---------------------------------------------------------------------------
// cp.async 2-stage pipelined bf16x3 GEMM, single __syncthreads per k-block.
// Order per iter: wait copy(kb) -> barrier -> issue copy(kb+1) -> compute(kb).
// Copy kb+1 targets stage (kb-1)&1, whose readers finished before this barrier.
// ---------------------------------------------------------------------------
#define PBM 128
#define PBN 128
#define PBK 32
#define PLDA 40
#define PSTAGE (PBM * PLDA)
#define GEMM_SMEM (2 * 4 * PSTAGE * 2)      // 81920 B

__global__ __launch_bounds__(256, 2) void gemm_async_kernel(
    const __nv_bfloat16* __restrict__ Ah, const __nv_bfloat16* __restrict__ Al,
    const __nv_bfloat16* __restrict__ Wh, const __nv_bfloat16* __restrict__ Wl,
    const float* __restrict__ bias, float* __restrict__ C, int act)
{
    extern __shared__ __nv_bfloat16 sm[];

    const int tid = threadIdx.x;
    const int wid = tid >> 5, lane = tid & 31;
    const int bm = blockIdx.y * PBM, bn = blockIdx.x * PBN;
    const int wm = (wid >> 2) * 64, wn = (wid & 3) * 32;

    const int cr = tid >> 1;
    const int cc = (tid & 1) * 16;

    float acc[4][4][4];
#pragma unroll
    for (int a = 0; a < 4; a++)
#pragma unroll
        for (int b = 0; b < 4; b++)
#pragma unroll
            for (int c = 0; c < 4; c++) acc[a][b][c] = 0.0f;

    auto copy_stage = [&](int s, int kb) {
        __nv_bfloat16* base = sm + (size_t)s * 4 * PSTAGE;
        const int kc = kb * PBK + cc;
        unsigned d = smaddr(&base[cr * PLDA + cc]);
        const size_t ga = (size_t)(bm + cr) * 1024 + kc;
        const size_t gw = (size_t)(bn + cr) * 1024 + kc;
        cp_async16(d,                          &Ah[ga]);
        cp_async16(d + 16,                     &Ah[ga + 8]);
        cp_async16(d + 1 * PSTAGE * 2,         &Al[ga]);
        cp_async16(d + 1 * PSTAGE * 2 + 16,    &Al[ga + 8]);
        cp_async16(d + 2 * PSTAGE * 2,         &Wh[gw]);
        cp_async16(d + 2 * PSTAGE * 2 + 16,    &Wh[gw + 8]);
        cp_async16(d + 3 * PSTAGE * 2,         &Wl[gw]);
        cp_async16(d + 3 * PSTAGE * 2 + 16,    &Wl[gw + 8]);
    };

    copy_stage(0, 0);
    cp_commit();

    const int NKB = 1024 / PBK;   // 32
    for (int kb = 0; kb < NKB; kb++) {
        cp_wait<0>();             // drain copy(kb) -- only outstanding group
        __syncthreads();          // all threads see stage kb; stage kb-1 free
        if (kb + 1 < NKB) {
            copy_stage((kb + 1) & 1, kb + 1);
            cp_commit();
        }

        {
            const __nv_bfloat16* bAh = sm + (size_t)(kb & 1) * 4 * PSTAGE;
            const __nv_bfloat16* bAl = bAh + PSTAGE;
            const __nv_bfloat16* bWh = bAl + PSTAGE;
            const __nv_bfloat16* bWl = bWh + PSTAGE;
#pragma unroll
            for (int kk = 0; kk < PBK; kk += 16) {
                unsigned ah[4][4], al[4][4], bh[2][4], bl[2][4];
#pragma unroll
                for (int mt = 0; mt < 4; mt++) {
                    int row = wm + mt * 16 + (lane & 15);
                    int col = kk + (lane >> 4) * 8;
                    ldsm_x4(ah[mt], smaddr(&bAh[row * PLDA + col]));
                    ldsm_x4(al[mt], smaddr(&bAl[row * PLDA + col]));
                }
#pragma unroll
                for (int p = 0; p < 2; p++) {
                    int row = wn + p * 16 + ((lane >> 4) & 1) * 8 + (lane & 7);
                    int col = kk + ((lane >> 3) & 1) * 8;
                    ldsm_x4(bh[p], smaddr(&bWh[row * PLDA + col]));
                    ldsm_x4(bl[p], smaddr(&bWl[row * PLDA + col]));
                }
#pragma unroll
                for (int mt = 0; mt < 4; mt++) {
#pragma unroll
                    for (int nt = 0; nt < 4; nt++) {
                        unsigned bhf[2] = { bh[nt >> 1][(nt & 1) * 2],
                                            bh[nt >> 1][(nt & 1) * 2 + 1] };
                        unsigned blf[2] = { bl[nt >> 1][(nt & 1) * 2],
                                            bl[nt >> 1][(nt & 1) * 2 + 1] };
                        mma_bf16(acc[mt][nt], ah[mt], bhf);
                        mma_bf16(acc[mt][nt], ah[mt], blf);
                        mma_bf16(acc[mt][nt], al[mt], bhf);
                    }
                }
            }
        }
    }

    const int g = lane >> 2, t = lane & 3;
#pragma unroll
    for (int mt = 0; mt < 4; mt++) {
#pragma unroll
        for (int nt = 0; nt < 4; nt++) {
            int row = bm + wm + mt * 16 + g;
            int col = bn + wn + nt * 8 + t * 2;
            float b0 = bias[col], b1 = bias[col + 1];
            float c0 = acc[mt][nt][0] + b0;
            float c1 = acc[mt][nt][1] + b1;
            float c2 = acc[mt][nt][2] + b0;
            float c3 = acc[mt][nt][3] + b1;
            if (act) {
                c0 = 1.0f / (1.0f + __expf(-c0));
                c1 = 1.0f / (1.0f + __expf(-c1));
                c2 = 1.0f / (1.0f + __expf(-c2));
                c3 = 1.0f / (1.0f + __expf(-c3));
            }
            *reinterpret_cast<float2*>(&C[(size_t)row * 1024 + col]) = make_float2(c0, c1);
            *reinterpret_cast<float2*>(&C[(size_t)(row + 8) * 1024 + col]) = make_float2(c2, c3);
        }
    }
}

// ---------------------------------------------------------------------------
// Fused RoPE + split + transpose; Q and K in one launch.
// ---------------------------------------------------------------------------
__global__ void qk_prep2_kernel(const float* __restrict__ Qsrc,
                                const float* __restrict__ Ksrc,
                                const float* __restrict__ cosb,
                                const float* __restrict__ sinb,
                                __nv_bfloat16* __restrict__ Qhi,
                                __nv_bfloat16* __restrict__ Qlo,
                                __nv_bfloat16* __restrict__ Khi,
                                __nv_bfloat16* __restrict__ Klo)
{
    const float* X = blockIdx.y ? Ksrc : Qsrc;
    __nv_bfloat16* hi = blockIdx.y ? Khi : Qhi;
    __nv_bfloat16* lo = blockIdx.y ? Klo : Qlo;

    int bl = blockIdx.x;
    int b = bl >> 10, l = bl & 1023;
    int h = threadIdx.x >> 4, j = threadIdx.x & 15;
    int d0 = j * 2;

    size_t ibase = (size_t)bl * D_ + h * HD_;
    size_t obase = ((size_t)(b * H_ + h) * LK_ + l) * HD_;
    size_t cbase = (size_t)bl * HD_;

    float x0 = X[ibase + d0],      x1 = X[ibase + d0 + 1];
    float y0 = X[ibase + d0 + 32], y1 = X[ibase + d0 + 33];
    float cA0 = cosb[cbase + d0],      sA0 = sinb[cbase + d0];
    float cA1 = cosb[cbase + d0 + 1],  sA1 = sinb[cbase + d0 + 1];
    float cB0 = cosb[cbase + d0 + 32], sB0 = sinb[cbase + d0 + 32];
    float cB1 = cosb[cbase + d0 + 33], sB1 = sinb[cbase + d0 + 33];

    float r0 = x0 * cA0 - y0 * sA0;
    float r1 = x1 * cA1 - y1 * sA1;
    float r2 = y0 * cB0 + x0 * sB0;
    float r3 = y1 * cB1 + x1 * sB1;

    __nv_bfloat16 h0 = __float2bfloat16_rn(r0), h1 = __float2bfloat16_rn(r1);
    __nv_bfloat16 h2 = __float2bfloat16_rn(r2), h3 = __float2bfloat16_rn(r3);
    __nv_bfloat162 hp0; hp0.x = h0; hp0.y = h1;
    __nv_bfloat162 hp1; hp1.x = h2; hp1.y = h3;
    __nv_bfloat162 lp0;
    lp0.x = __float2bfloat16_rn(r0 - __bfloat162float(h0));
    lp0.y = __float2bfloat16_rn(r1 - __bfloat162float(h1));
    __nv_bfloat162 lp1;
    lp1.x = __float2bfloat16_rn(r2 - __bfloat162float(h2));
    lp1.y = __float2bfloat16_rn(r3 - __bfloat162float(h3));

    *reinterpret_cast<__nv_bfloat162*>(&hi[obase + d0]) = hp0;
    *reinterpret_cast<__nv_bfloat162*>(&hi[obase + d0 + 32]) = hp1;
    *reinterpret_cast<__nv_bfloat162*>(&lo[obase + d0]) = lp0;
    *reinterpret_cast<__nv_bfloat162*>(&lo[obase + d0 + 32]) = lp1;
}

__global__ void v_prep_kernel(const float* __restrict__ X,
                              __nv_bfloat16* __restrict__ hi,
                              __nv_bfloat16* __restrict__ lo)
{
    int bl = blockIdx.x;
    int b = bl >> 10, l = bl & 1023;
    int h = threadIdx.x >> 4, j = threadIdx.x & 15;
    int d0 = j * 4;

    size_t ibase = (size_t)bl * D_ + h * HD_ + d0;
    size_t obase = ((size_t)(b * H_ + h) * LK_ + l) * HD_ + d0;

    float4 v = *reinterpret_cast<const float4*>(&X[ibase]);
    float vv[4] = {v.x, v.y, v.z, v.w};
    __nv_bfloat16 hh[4], ll[4];
#pragma unroll
    for (int i = 0; i < 4; i++) {
        hh[i] = __float2bfloat16_rn(vv[i]);
        ll[i] = __float2bfloat16_rn(vv[i] - __bfloat162float(hh[i]));
    }
    *reinterpret_cast<uint2*>(&hi[obase]) = *reinterpret_cast<uint2*>(hh);
    *reinterpret_cast<uint2*>(&lo[obase]) = *reinterpret_cast<uint2*>(ll);
}

// ---------------------------------------------------------------------------
// Tensor-core flash attention (bf16x3), unchanged (passing since R5).
// ---------------------------------------------------------------------------
#define AP 72
#define ATTN_SMEM (6 * 64 * AP * 2 + 64 * 4)

__global__ __launch_bounds__(128) void attn_mma_kernel(
    const __nv_bfloat16* __restrict__ Qh, const __nv_bfloat16* __restrict__ Ql,
    const __nv_bfloat16* __restrict__ Kh, const __nv_bfloat16* __restrict__ Kl,
    const __nv_bfloat16* __restrict__ Vh, const __nv_bfloat16* __restrict__ Vl,
    const unsigned char* __restrict__ mask, float* __restrict__ O)
{
    extern __shared__ char smraw[];
    __nv_bfloat16* sQh = reinterpret_cast<__nv_bfloat16*>(smraw);
    __nv_bfloat16* sQl = sQh + 64 * AP;
    __nv_bfloat16* sKh = sQl + 64 * AP;
    __nv_bfloat16* sKl = sKh + 64 * AP;
    __nv_bfloat16* sVh = sKl + 64 * AP;
    __nv_bfloat16* sVl = sVh + 64 * AP;
    float* sMask = reinterpret_cast<float*>(sVl + 64 * AP);

    const int tid = threadIdx.x;
    const int w = tid >> 5, lane = tid & 31;
    const int q0 = blockIdx.x * 64;
    const int h = blockIdx.y, b = blockIdx.z;
    const size_t headbase = (size_t)(b * H_ + h) * LK_ * HD_;
    const size_t qbase = headbase + (size_t)q0 * HD_;

#pragma unroll
    for (int it = 0; it < 4; it++) {
        int idx = tid + it * 128;
        int r = idx >> 3, c = (idx & 7) * 8;
        *reinterpret_cast<uint4*>(&sQh[r * AP + c]) =
            *reinterpret_cast<const uint4*>(&Qh[qbase + (size_t)r * HD_ + c]);
        *reinterpret_cast<uint4*>(&sQl[r * AP + c]) =
            *reinterpret_cast<const uint4*>(&Ql[qbase + (size_t)r * HD_ + c]);
    }
    __syncthreads();

    unsigned qh[4][4], ql[4][4];
    {
        int row = w * 16 + (lane & 15);
#pragma unroll
        for (int kk = 0; kk < 4; kk++) {
            int col = kk * 16 + (lane >> 4) * 8;
            ldsm_x4(qh[kk], smaddr(&sQh[row * AP + col]));
            ldsm_x4(ql[kk], smaddr(&sQl[row * AP + col]));
        }
    }

    float m0 = -3.0e38f, m1 = -3.0e38f, l0 = 0.0f, l1 = 0.0f;
    float Oacc[8][4];
#pragma unroll
    for (int nt = 0; nt < 8; nt++)
#pragma unroll
        for (int r = 0; r < 4; r++) Oacc[nt][r] = 0.0f;

    const int t = lane & 3;

    for (int k0 = 0; k0 < LK_; k0 += 64) {
        __syncthreads();
#pragma unroll
        for (int it = 0; it < 4; it++) {
            int idx = tid + it * 128;
            int r = idx >> 3, c = (idx & 7) * 8;
            size_t g = headbase + (size_t)(k0 + r) * HD_ + c;
            *reinterpret_cast<uint4*>(&sKh[r * AP + c]) =
                *reinterpret_cast<const uint4*>(&Kh[g]);
            *reinterpret_cast<uint4*>(&sKl[r * AP + c]) =
                *reinterpret_cast<const uint4*>(&Kl[g]);
            *reinterpret_cast<uint4*>(&sVh[r * AP + c]) =
                *reinterpret_cast<const uint4*>(&Vh[g]);
            *reinterpret_cast<uint4*>(&sVl[r * AP + c]) =
                *reinterpret_cast<const uint4*>(&Vl[g]);
        }
        if (tid < 64)
            sMask[tid] = mask[b * LK_ + k0 + tid] ? -1.0e30f : 0.0f;
        __syncthreads();

        float S[8][4];
#pragma unroll
        for (int nt = 0; nt < 8; nt++)
#pragma unroll
            for (int r = 0; r < 4; r++) S[nt][r] = 0.0f;

#pragma unroll
        for (int p = 0; p < 4; p++) {
#pragma unroll
            for (int kk = 0; kk < 4; kk++) {
                unsigned kbh[4], kbl[4];
                int row = p * 16 + ((lane >> 4) & 1) * 8 + (lane & 7);
                int col = kk * 16 + ((lane >> 3) & 1) * 8;
                ldsm_x4(kbh, smaddr(&sKh[row * AP + col]));
                ldsm_x4(kbl, smaddr(&sKl[row * AP + col]));
#pragma unroll
                for (int sub = 0; sub < 2; sub++) {
                    unsigned bh2[2] = {kbh[sub * 2], kbh[sub * 2 + 1]};
                    unsigned bl2[2] = {kbl[sub * 2], kbl[sub * 2 + 1]};
                    mma_bf16(S[2 * p + sub], qh[kk], bh2);
                    mma_bf16(S[2 * p + sub], qh[kk], bl2);
                    mma_bf16(S[2 * p + sub], ql[kk], bh2);
                }
            }
        }

        float rmax0 = -3.0e38f, rmax1 = -3.0e38f;
#pragma unroll
        for (int nt = 0; nt < 8; nt++) {
            float mv0 = sMask[nt * 8 + t * 2];
            float mv1 = sMask[nt * 8 + t * 2 + 1];
            S[nt][0] = S[nt][0] * 0.125f + mv0;
            S[nt][1] = S[nt][1] * 0.125f + mv1;
            S[nt][2] = S[nt][2] * 0.125f + mv0;
            S[nt][3] = S[nt][3] * 0.125f + mv1;
            rmax0 = fmaxf(rmax0, fmaxf(S[nt][0], S[nt][1]));
            rmax1 = fmaxf(rmax1, fmaxf(S[nt][2], S[nt][3]));
        }
        rmax0 = fmaxf(rmax0, __shfl_xor_sync(0xffffffffu, rmax0, 1));
        rmax0 = fmaxf(rmax0, __shfl_xor_sync(0xffffffffu, rmax0, 2));
        rmax1 = fmaxf(rmax1, __shfl_xor_sync(0xffffffffu, rmax1, 1));
        rmax1 = fmaxf(rmax1, __shfl_xor_sync(0xffffffffu, rmax1, 2));

        float mn0 = fmaxf(m0, rmax0), mn1 = fmaxf(m1, rmax1);
        float a0 = __expf(m0 - mn0), a1 = __expf(m1 - mn1);
        m0 = mn0; m1 = mn1;

        float rs0 = 0.0f, rs1 = 0.0f;
#pragma unroll
        for (int nt = 0; nt < 8; nt++) {
            S[nt][0] = __expf(S[nt][0] - m0);
            S[nt][1] = __expf(S[nt][1] - m0);
            S[nt][2] = __expf(S[nt][2] - m1);
            S[nt][3] = __expf(S[nt][3] - m1);
            rs0 += S[nt][0] + S[nt][1];
            rs1 += S[nt][2] + S[nt][3];
        }
        rs0 += __shfl_xor_sync(0xffffffffu, rs0, 1);
        rs0 += __shfl_xor_sync(0xffffffffu, rs0, 2);
        rs1 += __shfl_xor_sync(0xffffffffu, rs1, 1);
        rs1 += __shfl_xor_sync(0xffffffffu, rs1, 2);
        l0 = l0 * a0 + rs0;
        l1 = l1 * a1 + rs1;
#pragma unroll
        for (int nt = 0; nt < 8; nt++) {
            Oacc[nt][0] *= a0; Oacc[nt][1] *= a0;
            Oacc[nt][2] *= a1; Oacc[nt][3] *= a1;
        }

#pragma unroll
        for (int j = 0; j < 4; j++) {
            unsigned ah4[4], al4[4];
#pragma unroll
            for (int s2 = 0; s2 < 2; s2++) {
                int nt = 2 * j + s2;
                float p0 = S[nt][0], p1 = S[nt][1];
                float p2 = S[nt][2], p3 = S[nt][3];
                __nv_bfloat162 h01 = __floats2bfloat162_rn(p0, p1);
                __nv_bfloat162 h23 = __floats2bfloat162_rn(p2, p3);
                __nv_bfloat162 l01 = __floats2bfloat162_rn(
                    p0 - __bfloat162float(h01.x), p1 - __bfloat162float(h01.y));
                __nv_bfloat162 l23 = __floats2bfloat162_rn(
                    p2 - __bfloat162float(h23.x), p3 - __bfloat162float(h23.y));
                ah4[s2 * 2]     = *reinterpret_cast<unsigned*>(&h01);
                ah4[s2 * 2 + 1] = *reinterpret_cast<unsigned*>(&h23);
                al4[s2 * 2]     = *reinterpret_cast<unsigned*>(&l01);
                al4[s2 * 2 + 1] = *reinterpret_cast<unsigned*>(&l23);
            }
#pragma unroll
            for (int q = 0; q < 4; q++) {
                unsigned vbh[4], vbl[4];
                int row = j * 16 + ((lane >> 3) & 1) * 8 + (lane & 7);
                int col = q * 16 + ((lane >> 4) & 1) * 8;
                ldsm_x4_t(vbh, smaddr(&sVh[row * AP + col]));
                ldsm_x4_t(vbl, smaddr(&sVl[row * AP + col]));
#pragma unroll
                for (int sub = 0; sub < 2; sub++) {
                    unsigned bh2[2] = {vbh[sub * 2], vbh[sub * 2 + 1]};
                    unsigned bl2[2] = {vbl[sub * 2], vbl[sub * 2 + 1]};
                    mma_bf16(Oacc[2 * q + sub], ah4, bh2);
                    mma_bf16(Oacc[2 * q + sub], ah4, bl2);
                    mma_bf16(Oacc[2 * q + sub], al4, bh2);
                }
            }
        }
    }

    float inv0 = 1.0f / l0, inv1 = 1.0f / l1;
    const int g = lane >> 2;
    int row0 = q0 + w * 16 + g;
#pragma unroll
    for (int nt = 0; nt < 8; nt++) {
        int col = h * HD_ + nt * 8 + t * 2;
        *reinterpret_cast<float2*>(
            &O[((size_t)(b * LQ_) + row0) * D_ + col]) =
            make_float2(Oacc[nt][0] * inv0, Oacc[nt][1] * inv0);
        *reinterpret_cast<float2*>(
            &O[((size_t)(b * LQ_) + row0 + 8) * D_ + col]) =
            make_float2(Oacc[nt][2] * inv1, Oacc[nt][3] * inv1);
    }
}

// ---------------------------------------------------------------------------
extern "C" void kernel_launch(void* const* d_in, const int* in_sizes, int n_in,
                              void* d_out, int out_size)
{
    const float* query = (const float*)d_in[0];
    const float* key   = (const float*)d_in[1];
    const float* value = (const float*)d_in[2];
    const float* Wq = (const float*)d_in[3];
    const float* bq = (const float*)d_in[4];
    const float* Wk = (const float*)d_in[5];
    const float* bk = (const float*)d_in[6];
    const float* Wv = (const float*)d_in[7];
    const float* bv = (const float*)d_in[8];
    const float* Wg = (const float*)d_in[9];
    const float* bg = (const float*)d_in[10];
    const float* Wo = (const float*)d_in[11];
    const float* bo = (const float*)d_in[12];
    const float* rc = (const float*)d_in[13];
    const float* rs = (const float*)d_in[14];
    const unsigned char* mask = (const unsigned char*)d_in[15];
    float* out = (float*)d_out;

    float *Qb, *Kb, *Vb, *Gb, *Ob;
    __nv_bfloat16 *Xh, *Xl, *Wh5, *Wl5;
    __nv_bfloat16 *Qhh, *Qll, *Khh, *Kll, *Vhh, *Vll;
    cudaGetSymbolAddress((void**)&Qb, g_Q);
    cudaGetSymbolAddress((void**)&Kb, g_K);
    cudaGetSymbolAddress((void**)&Vb, g_V);
    cudaGetSymbolAddress((void**)&Gb, g_G);
    cudaGetSymbolAddress((void**)&Ob, g_O);
    cudaGetSymbolAddress((void**)&Xh, g_Xh);
    cudaGetSymbolAddress((void**)&Xl, g_Xl);
    cudaGetSymbolAddress((void**)&Wh5, g_Wh5);
    cudaGetSymbolAddress((void**)&Wl5, g_Wl5);
    cudaGetSymbolAddress((void**)&Qhh, g_Qh);
    cudaGetSymbolAddress((void**)&Qll, g_Ql);
    cudaGetSymbolAddress((void**)&Khh, g_Kh);
    cudaGetSymbolAddress((void**)&Kll, g_Kl);
    cudaGetSymbolAddress((void**)&Vhh, g_Vh);
    cudaGetSymbolAddress((void**)&Vll, g_Vl);

    cudaFuncSetAttribute(gemm_async_kernel,
                         cudaFuncAttributeMaxDynamicSharedMemorySize, GEMM_SMEM);
    cudaFuncSetAttribute(attn_mma_kernel,
                         cudaFuncAttributeMaxDynamicSharedMemorySize, ATTN_SMEM);

    const int na = (int)NELEM;
    dim3 ggrid(D_ / PBN, NTOK / PBM);   // (8, 64)

    // All splits up front (2 launches)
    split_w_all_kernel<<<5 * 1024, 256>>>(Wq, Wg, Wk, Wv, Wo, Wh5, Wl5);
    split_act3_kernel<<<3 * 8192, 256>>>(query, key, value, Xh, Xl);

    // 4 projections back-to-back
    gemm_async_kernel<<<ggrid, 256, GEMM_SMEM>>>(
        Xh, Xl, Wh5, Wl5, bq, Qb, 0);
    gemm_async_kernel<<<ggrid, 256, GEMM_SMEM>>>(
        Xh, Xl, Wh5 + (size_t)1 * NW, Wl5 + (size_t)1 * NW, bg, Gb, 1);
    gemm_async_kernel<<<ggrid, 256, GEMM_SMEM>>>(
        Xh + NELEM, Xl + NELEM, Wh5 + (size_t)2 * NW, Wl5 + (size_t)2 * NW, bk, Kb, 0);
    gemm_async_kernel<<<ggrid, 256, GEMM_SMEM>>>(
        Xh + 2 * NELEM, Xl + 2 * NELEM, Wh5 + (size_t)3 * NW, Wl5 + (size_t)3 * NW,
        bv, Vb, 0);

    // RoPE+split+transpose for Q,K (one launch) and V
    qk_prep2_kernel<<<dim3(B_ * LK_, 2), 256>>>(Qb, Kb, rc, rs, Qhh, Qll, Khh, Kll);
    v_prep_kernel<<<B_ * LK_, 256>>>(Vb, Vhh, Vll);

    // Tensor-core attention
    attn_mma_kernel<<<dim3(LQ_ / 64, H_, B_), 128, ATTN_SMEM>>>(
        Qhh, Qll, Khh, Kll, Vhh, Vll, mask, Ob);

    // Gate-multiply + split into act slot 0, then output projection
    gate_split_kernel<<<na / 1024, 256>>>(Ob, Gb, Xh, Xl, na);
    gemm_async_kernel<<<ggrid, 256, GEMM_SMEM>>>(
        Xh, Xl, Wh5 + (size_t)4 * NW, Wl5 + (size_t)4 * NW, bo, out, 0);
}